// round 5
// baseline (speedup 1.0000x reference)
#include <cuda_runtime.h>
#include <math.h>
#include <stdint.h>

#define BSZ 4
#define SSZ 2048
#define ESZ 1024
#define HSZ 16
#define DSZ 64

#define APAD 68   // attn: pad for Q/K/P smem rows
#define VPAD 72   // attn: pad for V smem rows

// Scratch (allocation-free): Q/K/V laid out [B][H][S][D]; attn out [B][S][H][D]
__device__ float g_q[BSZ*HSZ*SSZ*DSZ];
__device__ float g_k[BSZ*HSZ*SSZ*DSZ];
__device__ float g_v[BSZ*HSZ*SSZ*DSZ];
__device__ float g_attn[BSZ*SSZ*HSZ*DSZ];

__device__ __forceinline__ uint32_t f2tf32(float x) {
    uint32_t r;
    asm("cvt.rna.tf32.f32 %0, %1;" : "=r"(r) : "f"(x));
    return r;
}

__device__ __forceinline__ void mma_tf32(float& d0, float& d1, float& d2, float& d3,
                                         uint32_t a0, uint32_t a1, uint32_t a2, uint32_t a3,
                                         uint32_t b0, uint32_t b1) {
    asm volatile(
        "mma.sync.aligned.m16n8k8.row.col.f32.tf32.tf32.f32 "
        "{%0,%1,%2,%3},{%4,%5,%6,%7},{%8,%9},{%0,%1,%2,%3};"
        : "+f"(d0), "+f"(d1), "+f"(d2), "+f"(d3)
        : "r"(a0), "r"(a1), "r"(a2), "r"(a3), "r"(b0), "r"(b1));
}

// ---------------------------------------------------------------------------
// 3xTF32 tensor-core GEMM, splits hoisted to smem-commit time.
// C = A[M,1024] * B[1024,N] + bias
// mode 0: N=3072, scatter into g_q/g_k/g_v with q-scale (QKV projection)
// mode 1: N=1024, A := g_attn, plain write to out (output projection)
// BM=BN=128, BK=32, 256 threads (8 warps, warp tile 64x32).
// Dynamic smem: AsB/AsS [128][36] + BsB/BsS [32][136] tf32 bits = 71680 B.
// ---------------------------------------------------------------------------
__global__ __launch_bounds__(256) void gemm_tc_kernel(
    const float* __restrict__ A, const float* __restrict__ Bm,
    const float* __restrict__ bias, float* __restrict__ out,
    const int* __restrict__ lidx, int N, int mode)
{
    const int K = 1024;
    extern __shared__ uint32_t smg[];
    uint32_t (*AsB)[36]  = (uint32_t(*)[36]) smg;                    // 4608
    uint32_t (*AsS)[36]  = (uint32_t(*)[36])(smg + 4608);            // 4608
    uint32_t (*BsB)[136] = (uint32_t(*)[136])(smg + 9216);           // 4352
    uint32_t (*BsS)[136] = (uint32_t(*)[136])(smg + 13568);          // 4352

    const float* Ap = (mode == 1) ? (const float*)g_attn : A;

    int tid = threadIdx.x;
    int bm = blockIdx.y;
    int bn = blockIdx.x;
    int lane = tid & 31, warp = tid >> 5;
    int wm = (warp >> 2) * 64;
    int wn = (warp & 3) * 32;
    int r = lane >> 2;
    int c = lane & 3;

    const float* Ab = Ap + (size_t)bm * 128 * K;
    const float* Bb = Bm + (size_t)bn * 128;

    int aM = tid >> 1;
    int aK = (tid & 1) * 16;
    int bK = tid >> 3;
    int bN = (tid & 7) * 16;

    float acc[4][4][4];
    #pragma unroll
    for (int mi = 0; mi < 4; mi++)
        #pragma unroll
        for (int ni = 0; ni < 4; ni++)
            #pragma unroll
            for (int e = 0; e < 4; e++) acc[mi][ni][e] = 0.f;

    float4 aPref[4], bPref[4];
    #pragma unroll
    for (int j = 0; j < 4; j++) {
        aPref[j] = *(const float4*)(Ab + (size_t)aM * K + aK + j * 4);
        bPref[j] = *(const float4*)(Bb + (size_t)bK * N + bN + j * 4);
    }

    for (int k0 = 0; k0 < K; k0 += 32) {
        // commit prefetched tile: split into (big, small) tf32 pairs
        #pragma unroll
        for (int j = 0; j < 4; j++) {
            float4 a4 = aPref[j];
            uint4 ab, as;
            ab.x = f2tf32(a4.x); as.x = f2tf32(a4.x - __uint_as_float(ab.x));
            ab.y = f2tf32(a4.y); as.y = f2tf32(a4.y - __uint_as_float(ab.y));
            ab.z = f2tf32(a4.z); as.z = f2tf32(a4.z - __uint_as_float(ab.z));
            ab.w = f2tf32(a4.w); as.w = f2tf32(a4.w - __uint_as_float(ab.w));
            *(uint4*)&AsB[aM][aK + j * 4] = ab;
            *(uint4*)&AsS[aM][aK + j * 4] = as;

            float4 b4 = bPref[j];
            uint4 bb, bs;
            bb.x = f2tf32(b4.x); bs.x = f2tf32(b4.x - __uint_as_float(bb.x));
            bb.y = f2tf32(b4.y); bs.y = f2tf32(b4.y - __uint_as_float(bb.y));
            bb.z = f2tf32(b4.z); bs.z = f2tf32(b4.z - __uint_as_float(bb.z));
            bb.w = f2tf32(b4.w); bs.w = f2tf32(b4.w - __uint_as_float(bb.w));
            *(uint4*)&BsB[bK][bN + j * 4] = bb;
            *(uint4*)&BsS[bK][bN + j * 4] = bs;
        }
        __syncthreads();

        if (k0 + 32 < K) {
            #pragma unroll
            for (int j = 0; j < 4; j++) {
                aPref[j] = *(const float4*)(Ab + (size_t)aM * K + k0 + 32 + aK + j * 4);
                bPref[j] = *(const float4*)(Bb + (size_t)(k0 + 32 + bK) * N + bN + j * 4);
            }
        }

        #pragma unroll
        for (int ks = 0; ks < 4; ks++) {
            int k8 = ks * 8;
            uint32_t abig[4][4], asml[4][4];
            #pragma unroll
            for (int mi = 0; mi < 4; mi++) {
                int mrow = wm + mi * 16 + r;
                abig[mi][0] = AsB[mrow][k8 + c];
                abig[mi][1] = AsB[mrow + 8][k8 + c];
                abig[mi][2] = AsB[mrow][k8 + c + 4];
                abig[mi][3] = AsB[mrow + 8][k8 + c + 4];
                asml[mi][0] = AsS[mrow][k8 + c];
                asml[mi][1] = AsS[mrow + 8][k8 + c];
                asml[mi][2] = AsS[mrow][k8 + c + 4];
                asml[mi][3] = AsS[mrow + 8][k8 + c + 4];
            }
            uint32_t bbig[4][2], bsml[4][2];
            #pragma unroll
            for (int ni = 0; ni < 4; ni++) {
                int ncol = wn + ni * 8 + r;
                bbig[ni][0] = BsB[k8 + c][ncol];
                bbig[ni][1] = BsB[k8 + c + 4][ncol];
                bsml[ni][0] = BsS[k8 + c][ncol];
                bsml[ni][1] = BsS[k8 + c + 4][ncol];
            }
            #pragma unroll
            for (int mi = 0; mi < 4; mi++)
                #pragma unroll
                for (int ni = 0; ni < 4; ni++) {
                    float* d = acc[mi][ni];
                    mma_tf32(d[0], d[1], d[2], d[3],
                             abig[mi][0], abig[mi][1], abig[mi][2], abig[mi][3],
                             bbig[ni][0], bbig[ni][1]);
                    mma_tf32(d[0], d[1], d[2], d[3],
                             abig[mi][0], abig[mi][1], abig[mi][2], abig[mi][3],
                             bsml[ni][0], bsml[ni][1]);
                    mma_tf32(d[0], d[1], d[2], d[3],
                             asml[mi][0], asml[mi][1], asml[mi][2], asml[mi][3],
                             bbig[ni][0], bbig[ni][1]);
                }
        }
        __syncthreads();
    }

    if (mode == 0) {
        float scale = 0.125f / (float)(lidx[0] + 1);
        #pragma unroll
        for (int mi = 0; mi < 4; mi++) {
            #pragma unroll
            for (int ni = 0; ni < 4; ni++) {
                #pragma unroll
                for (int e = 0; e < 4; e++) {
                    int m = bm * 128 + wm + mi * 16 + r + (e >> 1) * 8;
                    int n = bn * 128 + wn + ni * 8 + c * 2 + (e & 1);
                    float v = acc[mi][ni][e] + bias[n];
                    int b = m >> 11, s = m & 2047;
                    int t = n >> 10;
                    int hd = n & 1023;
                    int h = hd >> 6, d = hd & 63;
                    size_t idx = ((size_t)(b * HSZ + h) * SSZ + s) * DSZ + d;
                    if (t == 0)      g_q[idx] = v * scale;
                    else if (t == 1) g_k[idx] = v;
                    else             g_v[idx] = v;
                }
            }
        }
    } else {
        #pragma unroll
        for (int mi = 0; mi < 4; mi++) {
            #pragma unroll
            for (int ni = 0; ni < 4; ni++) {
                #pragma unroll
                for (int e = 0; e < 4; e++) {
                    int m = bm * 128 + wm + mi * 16 + r + (e >> 1) * 8;
                    int n = bn * 128 + wn + ni * 8 + c * 2 + (e & 1);
                    out[(size_t)m * N + n] = acc[mi][ni][e] + bias[n];
                }
            }
        }
    }
}

// ---------------------------------------------------------------------------
// Tensor-core flash attention (unchanged from R3).
// ---------------------------------------------------------------------------
__global__ __launch_bounds__(256, 1) void attn_tc_kernel()
{
    extern __shared__ float sm[];
    float (*Ks)[APAD] = (float(*)[APAD])sm;
    float (*Vs)[VPAD] = (float(*)[VPAD])(sm + 64 * APAD);
    float (*Ps)[APAD] = (float(*)[APAD])(sm + 64 * APAD + 64 * VPAD);

    int bh = blockIdx.y;
    int qb = 15 - blockIdx.x;
    int q0 = qb * 128;

    const float* qp = g_q + (size_t)bh * SSZ * DSZ + (size_t)q0 * DSZ;
    const float* kb = g_k + (size_t)bh * SSZ * DSZ;
    const float* vb = g_v + (size_t)bh * SSZ * DSZ;

    int tid = threadIdx.x, lane = tid & 31, warp = tid >> 5;
    int r = lane >> 2, c = lane & 3;
    int wr0 = warp * 16;

    {
        float (*Qs)[APAD] = (float(*)[APAD])sm;
        for (int i = tid; i < 128 * 16; i += 256) {
            int row = i >> 4, col4 = (i & 15) * 4;
            *(float4*)&Qs[row][col4] = *(const float4*)(qp + row * 64 + col4);
        }
        __syncthreads();
    }
    uint32_t qa[8][4];
    {
        float (*Qs)[APAD] = (float(*)[APAD])sm;
        #pragma unroll
        for (int ks = 0; ks < 8; ks++) {
            int k8 = ks * 8;
            qa[ks][0] = f2tf32(Qs[wr0 + r][k8 + c]);
            qa[ks][1] = f2tf32(Qs[wr0 + r + 8][k8 + c]);
            qa[ks][2] = f2tf32(Qs[wr0 + r][k8 + c + 4]);
            qa[ks][3] = f2tf32(Qs[wr0 + r + 8][k8 + c + 4]);
        }
    }

    float m0 = -1e30f, m1 = -1e30f, l0 = 0.f, l1 = 0.f;
    float o[8][4];
    #pragma unroll
    for (int ni = 0; ni < 8; ni++)
        #pragma unroll
        for (int e = 0; e < 4; e++) o[ni][e] = 0.f;

    int qrow0 = q0 + wr0 + r;
    int qrow1 = qrow0 + 8;

    int ntiles = (qb + 1) * 2;
    for (int kt = 0; kt < ntiles; kt++) {
        __syncthreads();
        const float* kp = kb + (size_t)kt * 64 * DSZ;
        const float* vp = vb + (size_t)kt * 64 * DSZ;
        for (int i = tid; i < 1024; i += 256) {
            int row = i >> 4, col4 = (i & 15) * 4;
            *(float4*)&Ks[row][col4] = *(const float4*)(kp + row * 64 + col4);
            *(float4*)&Vs[row][col4] = *(const float4*)(vp + row * 64 + col4);
        }
        __syncthreads();

        float s[8][4];
        #pragma unroll
        for (int ni = 0; ni < 8; ni++)
            #pragma unroll
            for (int e = 0; e < 4; e++) s[ni][e] = 0.f;

        #pragma unroll
        for (int ks = 0; ks < 8; ks++) {
            int k8 = ks * 8;
            #pragma unroll
            for (int ni = 0; ni < 8; ni++) {
                uint32_t b0 = f2tf32(Ks[ni * 8 + r][k8 + c]);
                uint32_t b1 = f2tf32(Ks[ni * 8 + r][k8 + c + 4]);
                mma_tf32(s[ni][0], s[ni][1], s[ni][2], s[ni][3],
                         qa[ks][0], qa[ks][1], qa[ks][2], qa[ks][3], b0, b1);
            }
        }

        if (kt * 64 + 63 > qrow0) {
            #pragma unroll
            for (int ni = 0; ni < 8; ni++) {
                int key = kt * 64 + ni * 8 + 2 * c;
                if (key     > qrow0) s[ni][0] = -1e30f;
                if (key + 1 > qrow0) s[ni][1] = -1e30f;
                if (key     > qrow1) s[ni][2] = -1e30f;
                if (key + 1 > qrow1) s[ni][3] = -1e30f;
            }
        }

        float mx0 = -1e30f, mx1 = -1e30f;
        #pragma unroll
        for (int ni = 0; ni < 8; ni++) {
            mx0 = fmaxf(mx0, fmaxf(s[ni][0], s[ni][1]));
            mx1 = fmaxf(mx1, fmaxf(s[ni][2], s[ni][3]));
        }
        mx0 = fmaxf(mx0, __shfl_xor_sync(0xffffffffu, mx0, 1));
        mx0 = fmaxf(mx0, __shfl_xor_sync(0xffffffffu, mx0, 2));
        mx1 = fmaxf(mx1, __shfl_xor_sync(0xffffffffu, mx1, 1));
        mx1 = fmaxf(mx1, __shfl_xor_sync(0xffffffffu, mx1, 2));

        float mn0 = fmaxf(m0, mx0), mn1 = fmaxf(m1, mx1);
        float sum0 = 0.f, sum1 = 0.f;
        #pragma unroll
        for (int ni = 0; ni < 8; ni++) {
            float p0 = __expf(s[ni][0] - mn0);
            float p1 = __expf(s[ni][1] - mn0);
            float p2 = __expf(s[ni][2] - mn1);
            float p3 = __expf(s[ni][3] - mn1);
            sum0 += p0 + p1;
            sum1 += p2 + p3;
            *(float2*)&Ps[wr0 + r][ni * 8 + 2 * c]     = make_float2(p0, p1);
            *(float2*)&Ps[wr0 + r + 8][ni * 8 + 2 * c] = make_float2(p2, p3);
        }
        sum0 += __shfl_xor_sync(0xffffffffu, sum0, 1);
        sum0 += __shfl_xor_sync(0xffffffffu, sum0, 2);
        sum1 += __shfl_xor_sync(0xffffffffu, sum1, 1);
        sum1 += __shfl_xor_sync(0xffffffffu, sum1, 2);

        float alpha0 = __expf(m0 - mn0);
        float alpha1 = __expf(m1 - mn1);
        l0 = l0 * alpha0 + sum0;  m0 = mn0;
        l1 = l1 * alpha1 + sum1;  m1 = mn1;
        #pragma unroll
        for (int ni = 0; ni < 8; ni++) {
            o[ni][0] *= alpha0; o[ni][1] *= alpha0;
            o[ni][2] *= alpha1; o[ni][3] *= alpha1;
        }
        __syncwarp();

        #pragma unroll
        for (int ks = 0; ks < 8; ks++) {
            int k8 = ks * 8;
            float f0 = Ps[wr0 + r][k8 + c];
            float f1 = Ps[wr0 + r + 8][k8 + c];
            float f2 = Ps[wr0 + r][k8 + c + 4];
            float f3 = Ps[wr0 + r + 8][k8 + c + 4];
            uint32_t pb0 = f2tf32(f0), pb1 = f2tf32(f1), pb2 = f2tf32(f2), pb3 = f2tf32(f3);
            uint32_t ps0 = f2tf32(f0 - __uint_as_float(pb0));
            uint32_t ps1 = f2tf32(f1 - __uint_as_float(pb1));
            uint32_t ps2 = f2tf32(f2 - __uint_as_float(pb2));
            uint32_t ps3 = f2tf32(f3 - __uint_as_float(pb3));
            #pragma unroll
            for (int ni = 0; ni < 8; ni++) {
                float v0 = Vs[k8 + c][ni * 8 + r];
                float v1 = Vs[k8 + c + 4][ni * 8 + r];
                uint32_t vb0 = f2tf32(v0), vb1 = f2tf32(v1);
                uint32_t vs0 = f2tf32(v0 - __uint_as_float(vb0));
                uint32_t vs1 = f2tf32(v1 - __uint_as_float(vb1));
                mma_tf32(o[ni][0], o[ni][1], o[ni][2], o[ni][3],
                         pb0, pb1, pb2, pb3, vb0, vb1);
                mma_tf32(o[ni][0], o[ni][1], o[ni][2], o[ni][3],
                         ps0, ps1, ps2, ps3, vb0, vb1);
                mma_tf32(o[ni][0], o[ni][1], o[ni][2], o[ni][3],
                         pb0, pb1, pb2, pb3, vs0, vs1);
            }
        }
    }

    int b = bh >> 4, h = bh & 15;
    float inv0 = 1.f / l0, inv1 = 1.f / l1;
    int s0 = q0 + wr0 + r, s1 = s0 + 8;
    size_t base0 = ((size_t)(b * SSZ + s0) * HSZ + h) * DSZ;
    size_t base1 = ((size_t)(b * SSZ + s1) * HSZ + h) * DSZ;
    #pragma unroll
    for (int ni = 0; ni < 8; ni++) {
        int d0 = ni * 8 + 2 * c;
        *(float2*)&g_attn[base0 + d0] = make_float2(o[ni][0] * inv0, o[ni][1] * inv0);
        *(float2*)&g_attn[base1 + d0] = make_float2(o[ni][2] * inv1, o[ni][3] * inv1);
    }
}

extern "C" void kernel_launch(void* const* d_in, const int* in_sizes, int n_in,
                              void* d_out, int out_size)
{
    const float* hidden = (const float*)d_in[0];
    const float* Wqkv  = (const float*)d_in[2];
    const float* bqkv  = (const float*)d_in[3];
    const float* Wproj = (const float*)d_in[4];
    const float* bproj = (const float*)d_in[5];
    const int*   lidx  = (const int*)d_in[6];
    float* out = (float*)d_out;

    const int gemm_smem = 17920 * 4;   // 71680 B
    cudaFuncSetAttribute(gemm_tc_kernel,
        cudaFuncAttributeMaxDynamicSharedMemorySize, gemm_smem);
    int attn_smem = (64 * APAD + 64 * VPAD + 128 * APAD) * 4;
    cudaFuncSetAttribute(attn_tc_kernel,
        cudaFuncAttributeMaxDynamicSharedMemorySize, attn_smem);

    // QKV projection: M=8192, N=3072, K=1024
    gemm_tc_kernel<<<dim3(24, 64), 256, gemm_smem>>>(hidden, Wqkv, bqkv, nullptr, lidx, 3072, 0);
    // Attention: 16 query tiles (128 rows each) x 64 (b,h) pairs
    attn_tc_kernel<<<dim3(16, 64), 256, attn_smem>>>();
    // Output projection: M=8192, N=1024, K=1024 (A := g_attn inside kernel)
    gemm_tc_kernel<<<dim3(8, 64), 256, gemm_smem>>>(nullptr, Wproj, bproj, out, lidx, 1024, 1);
}

// round 6
// speedup vs baseline: 1.1780x; 1.1780x over previous
#include <cuda_runtime.h>
#include <math.h>
#include <stdint.h>

#define BSZ 4
#define SSZ 2048
#define ESZ 1024
#define HSZ 16
#define DSZ 64

#define APAD 68   // attn: pad for Q/K/P smem rows
#define VPAD 72   // attn: pad for V smem rows

// Scratch (allocation-free): Q/K/V laid out [B][H][S][D]; attn out [B][S][H][D]
__device__ float g_q[BSZ*HSZ*SSZ*DSZ];
__device__ float g_k[BSZ*HSZ*SSZ*DSZ];
__device__ float g_v[BSZ*HSZ*SSZ*DSZ];
__device__ float g_attn[BSZ*SSZ*HSZ*DSZ];

__device__ __forceinline__ uint32_t f2tf32(float x) {
    uint32_t r;
    asm("cvt.rna.tf32.f32 %0, %1;" : "=r"(r) : "f"(x));
    return r;
}

__device__ __forceinline__ void mma_tf32(float& d0, float& d1, float& d2, float& d3,
                                         uint32_t a0, uint32_t a1, uint32_t a2, uint32_t a3,
                                         uint32_t b0, uint32_t b1) {
    asm volatile(
        "mma.sync.aligned.m16n8k8.row.col.f32.tf32.tf32.f32 "
        "{%0,%1,%2,%3},{%4,%5,%6,%7},{%8,%9},{%0,%1,%2,%3};"
        : "+f"(d0), "+f"(d1), "+f"(d2), "+f"(d3)
        : "r"(a0), "r"(a1), "r"(a2), "r"(a3), "r"(b0), "r"(b1));
}

// ---------------------------------------------------------------------------
// 3xTF32 tensor-core GEMM, in-register splits (R3 style), 2 CTAs/SM.
// C = A[M,1024] * B[1024,N] + bias
// mode 0: N=3072, scatter into g_q/g_k/g_v with q-scale (QKV projection)
// mode 1: N=1024, A := g_attn, plain write to out (output projection)
// BM=128, BN=64, BK=32, 256 threads (8 warps as 4m x 2n, warp tile 32x32).
// Static smem 27.6 KB; __launch_bounds__(256,2) caps regs at 128 -> occ 25%.
// ---------------------------------------------------------------------------
__global__ __launch_bounds__(256, 2) void gemm_tc_kernel(
    const float* __restrict__ A, const float* __restrict__ Bm,
    const float* __restrict__ bias, float* __restrict__ out,
    const int* __restrict__ lidx, int N, int mode)
{
    const int K = 1024;
    __shared__ float As[128][36];   // bank = 4r + c  (bijective over warp)
    __shared__ float Bs[32][72];    // bank = 8c + r  (bijective over warp)

    const float* Ap = (mode == 1) ? (const float*)g_attn : A;

    int tid = threadIdx.x;
    int bm = blockIdx.y;
    int bn = blockIdx.x;
    int lane = tid & 31, warp = tid >> 5;
    int wm = (warp >> 1) * 32;      // 4 m-warps
    int wn = (warp & 1) * 32;       // 2 n-warps
    int r = lane >> 2;              // 0..7
    int c = lane & 3;               // 0..3

    const float* Ab = Ap + (size_t)bm * 128 * K;
    const float* Bb = Bm + (size_t)bn * 64;

    // gmem load assignment
    int aM = tid >> 1;              // 0..127
    int aK = (tid & 1) * 16;        // 0 or 16
    int bK = tid >> 3;              // 0..31
    int bN = (tid & 7) * 8;         // 0..56

    float acc[2][4][4];
    #pragma unroll
    for (int mi = 0; mi < 2; mi++)
        #pragma unroll
        for (int ni = 0; ni < 4; ni++)
            #pragma unroll
            for (int e = 0; e < 4; e++) acc[mi][ni][e] = 0.f;

    float4 aPref[4];
    float4 bPref[2];
    #pragma unroll
    for (int j = 0; j < 4; j++)
        aPref[j] = *(const float4*)(Ab + (size_t)aM * K + aK + j * 4);
    #pragma unroll
    for (int j = 0; j < 2; j++)
        bPref[j] = *(const float4*)(Bb + (size_t)bK * N + bN + j * 4);

    for (int k0 = 0; k0 < K; k0 += 32) {
        #pragma unroll
        for (int j = 0; j < 4; j++)
            *(float4*)&As[aM][aK + j * 4] = aPref[j];
        #pragma unroll
        for (int j = 0; j < 2; j++)
            *(float4*)&Bs[bK][bN + j * 4] = bPref[j];
        __syncthreads();

        if (k0 + 32 < K) {
            #pragma unroll
            for (int j = 0; j < 4; j++)
                aPref[j] = *(const float4*)(Ab + (size_t)aM * K + k0 + 32 + aK + j * 4);
            #pragma unroll
            for (int j = 0; j < 2; j++)
                bPref[j] = *(const float4*)(Bb + (size_t)(k0 + 32 + bK) * N + bN + j * 4);
        }

        #pragma unroll
        for (int ks = 0; ks < 4; ks++) {
            int k8 = ks * 8;
            uint32_t abig[2][4], asml[2][4];
            #pragma unroll
            for (int mi = 0; mi < 2; mi++) {
                int mrow = wm + mi * 16 + r;
                float a0 = As[mrow][k8 + c];
                float a1 = As[mrow + 8][k8 + c];
                float a2 = As[mrow][k8 + c + 4];
                float a3 = As[mrow + 8][k8 + c + 4];
                abig[mi][0] = f2tf32(a0); asml[mi][0] = f2tf32(a0 - __uint_as_float(abig[mi][0]));
                abig[mi][1] = f2tf32(a1); asml[mi][1] = f2tf32(a1 - __uint_as_float(abig[mi][1]));
                abig[mi][2] = f2tf32(a2); asml[mi][2] = f2tf32(a2 - __uint_as_float(abig[mi][2]));
                abig[mi][3] = f2tf32(a3); asml[mi][3] = f2tf32(a3 - __uint_as_float(abig[mi][3]));
            }
            uint32_t bbig[4][2], bsml[4][2];
            #pragma unroll
            for (int ni = 0; ni < 4; ni++) {
                int ncol = wn + ni * 8 + r;
                float b0 = Bs[k8 + c][ncol];
                float b1 = Bs[k8 + c + 4][ncol];
                bbig[ni][0] = f2tf32(b0); bsml[ni][0] = f2tf32(b0 - __uint_as_float(bbig[ni][0]));
                bbig[ni][1] = f2tf32(b1); bsml[ni][1] = f2tf32(b1 - __uint_as_float(bbig[ni][1]));
            }
            #pragma unroll
            for (int mi = 0; mi < 2; mi++)
                #pragma unroll
                for (int ni = 0; ni < 4; ni++) {
                    float* d = acc[mi][ni];
                    mma_tf32(d[0], d[1], d[2], d[3],
                             abig[mi][0], abig[mi][1], abig[mi][2], abig[mi][3],
                             bbig[ni][0], bbig[ni][1]);
                    mma_tf32(d[0], d[1], d[2], d[3],
                             abig[mi][0], abig[mi][1], abig[mi][2], abig[mi][3],
                             bsml[ni][0], bsml[ni][1]);
                    mma_tf32(d[0], d[1], d[2], d[3],
                             asml[mi][0], asml[mi][1], asml[mi][2], asml[mi][3],
                             bbig[ni][0], bbig[ni][1]);
                }
        }
        __syncthreads();
    }

    // Epilogue. acc elem e: row = r + (e>>1)*8, col = c*2 + (e&1)
    if (mode == 0) {
        float scale = 0.125f / (float)(lidx[0] + 1);
        #pragma unroll
        for (int mi = 0; mi < 2; mi++) {
            #pragma unroll
            for (int ni = 0; ni < 4; ni++) {
                #pragma unroll
                for (int e = 0; e < 4; e++) {
                    int m = bm * 128 + wm + mi * 16 + r + (e >> 1) * 8;
                    int n = bn * 64 + wn + ni * 8 + c * 2 + (e & 1);
                    float v = acc[mi][ni][e] + bias[n];
                    int b = m >> 11, s = m & 2047;
                    int t = n >> 10;
                    int hd = n & 1023;
                    int h = hd >> 6, d = hd & 63;
                    size_t idx = ((size_t)(b * HSZ + h) * SSZ + s) * DSZ + d;
                    if (t == 0)      g_q[idx] = v * scale;
                    else if (t == 1) g_k[idx] = v;
                    else             g_v[idx] = v;
                }
            }
        }
    } else {
        #pragma unroll
        for (int mi = 0; mi < 2; mi++) {
            #pragma unroll
            for (int ni = 0; ni < 4; ni++) {
                #pragma unroll
                for (int e = 0; e < 4; e++) {
                    int m = bm * 128 + wm + mi * 16 + r + (e >> 1) * 8;
                    int n = bn * 64 + wn + ni * 8 + c * 2 + (e & 1);
                    out[(size_t)m * N + n] = acc[mi][ni][e] + bias[n];
                }
            }
        }
    }
}

// ---------------------------------------------------------------------------
// Tensor-core flash attention (unchanged from R3).
// ---------------------------------------------------------------------------
__global__ __launch_bounds__(256, 1) void attn_tc_kernel()
{
    extern __shared__ float sm[];
    float (*Ks)[APAD] = (float(*)[APAD])sm;
    float (*Vs)[VPAD] = (float(*)[VPAD])(sm + 64 * APAD);
    float (*Ps)[APAD] = (float(*)[APAD])(sm + 64 * APAD + 64 * VPAD);

    int bh = blockIdx.y;
    int qb = 15 - blockIdx.x;
    int q0 = qb * 128;

    const float* qp = g_q + (size_t)bh * SSZ * DSZ + (size_t)q0 * DSZ;
    const float* kb = g_k + (size_t)bh * SSZ * DSZ;
    const float* vb = g_v + (size_t)bh * SSZ * DSZ;

    int tid = threadIdx.x, lane = tid & 31, warp = tid >> 5;
    int r = lane >> 2, c = lane & 3;
    int wr0 = warp * 16;

    {
        float (*Qs)[APAD] = (float(*)[APAD])sm;
        for (int i = tid; i < 128 * 16; i += 256) {
            int row = i >> 4, col4 = (i & 15) * 4;
            *(float4*)&Qs[row][col4] = *(const float4*)(qp + row * 64 + col4);
        }
        __syncthreads();
    }
    uint32_t qa[8][4];
    {
        float (*Qs)[APAD] = (float(*)[APAD])sm;
        #pragma unroll
        for (int ks = 0; ks < 8; ks++) {
            int k8 = ks * 8;
            qa[ks][0] = f2tf32(Qs[wr0 + r][k8 + c]);
            qa[ks][1] = f2tf32(Qs[wr0 + r + 8][k8 + c]);
            qa[ks][2] = f2tf32(Qs[wr0 + r][k8 + c + 4]);
            qa[ks][3] = f2tf32(Qs[wr0 + r + 8][k8 + c + 4]);
        }
    }

    float m0 = -1e30f, m1 = -1e30f, l0 = 0.f, l1 = 0.f;
    float o[8][4];
    #pragma unroll
    for (int ni = 0; ni < 8; ni++)
        #pragma unroll
        for (int e = 0; e < 4; e++) o[ni][e] = 0.f;

    int qrow0 = q0 + wr0 + r;
    int qrow1 = qrow0 + 8;

    int ntiles = (qb + 1) * 2;
    for (int kt = 0; kt < ntiles; kt++) {
        __syncthreads();
        const float* kp = kb + (size_t)kt * 64 * DSZ;
        const float* vp = vb + (size_t)kt * 64 * DSZ;
        for (int i = tid; i < 1024; i += 256) {
            int row = i >> 4, col4 = (i & 15) * 4;
            *(float4*)&Ks[row][col4] = *(const float4*)(kp + row * 64 + col4);
            *(float4*)&Vs[row][col4] = *(const float4*)(vp + row * 64 + col4);
        }
        __syncthreads();

        float s[8][4];
        #pragma unroll
        for (int ni = 0; ni < 8; ni++)
            #pragma unroll
            for (int e = 0; e < 4; e++) s[ni][e] = 0.f;

        #pragma unroll
        for (int ks = 0; ks < 8; ks++) {
            int k8 = ks * 8;
            #pragma unroll
            for (int ni = 0; ni < 8; ni++) {
                uint32_t b0 = f2tf32(Ks[ni * 8 + r][k8 + c]);
                uint32_t b1 = f2tf32(Ks[ni * 8 + r][k8 + c + 4]);
                mma_tf32(s[ni][0], s[ni][1], s[ni][2], s[ni][3],
                         qa[ks][0], qa[ks][1], qa[ks][2], qa[ks][3], b0, b1);
            }
        }

        if (kt * 64 + 63 > qrow0) {
            #pragma unroll
            for (int ni = 0; ni < 8; ni++) {
                int key = kt * 64 + ni * 8 + 2 * c;
                if (key     > qrow0) s[ni][0] = -1e30f;
                if (key + 1 > qrow0) s[ni][1] = -1e30f;
                if (key     > qrow1) s[ni][2] = -1e30f;
                if (key + 1 > qrow1) s[ni][3] = -1e30f;
            }
        }

        float mx0 = -1e30f, mx1 = -1e30f;
        #pragma unroll
        for (int ni = 0; ni < 8; ni++) {
            mx0 = fmaxf(mx0, fmaxf(s[ni][0], s[ni][1]));
            mx1 = fmaxf(mx1, fmaxf(s[ni][2], s[ni][3]));
        }
        mx0 = fmaxf(mx0, __shfl_xor_sync(0xffffffffu, mx0, 1));
        mx0 = fmaxf(mx0, __shfl_xor_sync(0xffffffffu, mx0, 2));
        mx1 = fmaxf(mx1, __shfl_xor_sync(0xffffffffu, mx1, 1));
        mx1 = fmaxf(mx1, __shfl_xor_sync(0xffffffffu, mx1, 2));

        float mn0 = fmaxf(m0, mx0), mn1 = fmaxf(m1, mx1);
        float sum0 = 0.f, sum1 = 0.f;
        #pragma unroll
        for (int ni = 0; ni < 8; ni++) {
            float p0 = __expf(s[ni][0] - mn0);
            float p1 = __expf(s[ni][1] - mn0);
            float p2 = __expf(s[ni][2] - mn1);
            float p3 = __expf(s[ni][3] - mn1);
            sum0 += p0 + p1;
            sum1 += p2 + p3;
            *(float2*)&Ps[wr0 + r][ni * 8 + 2 * c]     = make_float2(p0, p1);
            *(float2*)&Ps[wr0 + r + 8][ni * 8 + 2 * c] = make_float2(p2, p3);
        }
        sum0 += __shfl_xor_sync(0xffffffffu, sum0, 1);
        sum0 += __shfl_xor_sync(0xffffffffu, sum0, 2);
        sum1 += __shfl_xor_sync(0xffffffffu, sum1, 1);
        sum1 += __shfl_xor_sync(0xffffffffu, sum1, 2);

        float alpha0 = __expf(m0 - mn0);
        float alpha1 = __expf(m1 - mn1);
        l0 = l0 * alpha0 + sum0;  m0 = mn0;
        l1 = l1 * alpha1 + sum1;  m1 = mn1;
        #pragma unroll
        for (int ni = 0; ni < 8; ni++) {
            o[ni][0] *= alpha0; o[ni][1] *= alpha0;
            o[ni][2] *= alpha1; o[ni][3] *= alpha1;
        }
        __syncwarp();

        #pragma unroll
        for (int ks = 0; ks < 8; ks++) {
            int k8 = ks * 8;
            float f0 = Ps[wr0 + r][k8 + c];
            float f1 = Ps[wr0 + r + 8][k8 + c];
            float f2 = Ps[wr0 + r][k8 + c + 4];
            float f3 = Ps[wr0 + r + 8][k8 + c + 4];
            uint32_t pb0 = f2tf32(f0), pb1 = f2tf32(f1), pb2 = f2tf32(f2), pb3 = f2tf32(f3);
            uint32_t ps0 = f2tf32(f0 - __uint_as_float(pb0));
            uint32_t ps1 = f2tf32(f1 - __uint_as_float(pb1));
            uint32_t ps2 = f2tf32(f2 - __uint_as_float(pb2));
            uint32_t ps3 = f2tf32(f3 - __uint_as_float(pb3));
            #pragma unroll
            for (int ni = 0; ni < 8; ni++) {
                float v0 = Vs[k8 + c][ni * 8 + r];
                float v1 = Vs[k8 + c + 4][ni * 8 + r];
                uint32_t vb0 = f2tf32(v0), vb1 = f2tf32(v1);
                uint32_t vs0 = f2tf32(v0 - __uint_as_float(vb0));
                uint32_t vs1 = f2tf32(v1 - __uint_as_float(vb1));
                mma_tf32(o[ni][0], o[ni][1], o[ni][2], o[ni][3],
                         pb0, pb1, pb2, pb3, vb0, vb1);
                mma_tf32(o[ni][0], o[ni][1], o[ni][2], o[ni][3],
                         ps0, ps1, ps2, ps3, vb0, vb1);
                mma_tf32(o[ni][0], o[ni][1], o[ni][2], o[ni][3],
                         pb0, pb1, pb2, pb3, vs0, vs1);
            }
        }
    }

    int b = bh >> 4, h = bh & 15;
    float inv0 = 1.f / l0, inv1 = 1.f / l1;
    int s0 = q0 + wr0 + r, s1 = s0 + 8;
    size_t base0 = ((size_t)(b * SSZ + s0) * HSZ + h) * DSZ;
    size_t base1 = ((size_t)(b * SSZ + s1) * HSZ + h) * DSZ;
    #pragma unroll
    for (int ni = 0; ni < 8; ni++) {
        int d0 = ni * 8 + 2 * c;
        *(float2*)&g_attn[base0 + d0] = make_float2(o[ni][0] * inv0, o[ni][1] * inv0);
        *(float2*)&g_attn[base1 + d0] = make_float2(o[ni][2] * inv1, o[ni][3] * inv1);
    }
}

extern "C" void kernel_launch(void* const* d_in, const int* in_sizes, int n_in,
                              void* d_out, int out_size)
{
    const float* hidden = (const float*)d_in[0];
    const float* Wqkv  = (const float*)d_in[2];
    const float* bqkv  = (const float*)d_in[3];
    const float* Wproj = (const float*)d_in[4];
    const float* bproj = (const float*)d_in[5];
    const int*   lidx  = (const int*)d_in[6];
    float* out = (float*)d_out;

    int attn_smem = (64 * APAD + 64 * VPAD + 128 * APAD) * 4;
    cudaFuncSetAttribute(attn_tc_kernel,
        cudaFuncAttributeMaxDynamicSharedMemorySize, attn_smem);

    // QKV projection: M=8192, N=3072, K=1024  (BN=64 -> 48 n-blocks)
    gemm_tc_kernel<<<dim3(48, 64), 256>>>(hidden, Wqkv, bqkv, nullptr, lidx, 3072, 0);
    // Attention: 16 query tiles (128 rows each) x 64 (b,h) pairs
    attn_tc_kernel<<<dim3(16, 64), 256, attn_smem>>>();
    // Output projection: M=8192, N=1024, K=1024  (BN=64 -> 16 n-blocks)
    gemm_tc_kernel<<<dim3(16, 64), 256>>>(nullptr, Wproj, bproj, out, lidx, 1024, 1);
}

// round 8
// speedup vs baseline: 1.2653x; 1.0741x over previous
#include <cuda_runtime.h>
#include <math.h>
#include <stdint.h>

#define BSZ 4
#define SSZ 2048
#define ESZ 1024
#define HSZ 16
#define DSZ 64

#define APAD 68   // attn: pad for Q/K/P smem rows
#define VPAD 72   // attn: pad for V smem rows

// Scratch (allocation-free): Q/K/V laid out [B][H][S][D]; attn out [B][S][H][D]
__device__ float g_q[BSZ*HSZ*SSZ*DSZ];
__device__ float g_k[BSZ*HSZ*SSZ*DSZ];
__device__ float g_v[BSZ*HSZ*SSZ*DSZ];
__device__ float g_attn[BSZ*SSZ*HSZ*DSZ];

__device__ __forceinline__ uint32_t f2tf32(float x) {
    uint32_t r;
    asm("cvt.rna.tf32.f32 %0, %1;" : "=r"(r) : "f"(x));
    return r;
}

__device__ __forceinline__ void mma_tf32(float& d0, float& d1, float& d2, float& d3,
                                         uint32_t a0, uint32_t a1, uint32_t a2, uint32_t a3,
                                         uint32_t b0, uint32_t b1) {
    asm volatile(
        "mma.sync.aligned.m16n8k8.row.col.f32.tf32.tf32.f32 "
        "{%0,%1,%2,%3},{%4,%5,%6,%7},{%8,%9},{%0,%1,%2,%3};"
        : "+f"(d0), "+f"(d1), "+f"(d2), "+f"(d3)
        : "r"(a0), "r"(a1), "r"(a2), "r"(a3), "r"(b0), "r"(b1));
}

__device__ __forceinline__ void mma_bf16(float& d0, float& d1, float& d2, float& d3,
                                         uint32_t a0, uint32_t a1, uint32_t a2, uint32_t a3,
                                         uint32_t b0, uint32_t b1) {
    asm volatile(
        "mma.sync.aligned.m16n8k16.row.col.f32.bf16.bf16.f32 "
        "{%0,%1,%2,%3},{%4,%5,%6,%7},{%8,%9},{%0,%1,%2,%3};"
        : "+f"(d0), "+f"(d1), "+f"(d2), "+f"(d3)
        : "r"(a0), "r"(a1), "r"(a2), "r"(a3), "r"(b0), "r"(b1));
}

// Split (x0, x1) -> hi pack {bf16(x1):bf16(x0)} and lo pack of the residuals.
// Low 16 bits of the packed reg = first (lower-k) element, as the mma expects.
__device__ __forceinline__ void bsplit2(float x0, float x1, uint32_t& hi, uint32_t& lo) {
    uint32_t h;
    asm("cvt.rn.bf16x2.f32 %0, %1, %2;" : "=r"(h) : "f"(x1), "f"(x0));
    float h1 = __uint_as_float(h & 0xFFFF0000u);
    float h0 = __uint_as_float(h << 16);
    float r0 = x0 - h0;
    float r1 = x1 - h1;
    asm("cvt.rn.bf16x2.f32 %0, %1, %2;" : "=r"(lo) : "f"(r1), "f"(r0));
    hi = h;
}

// ---------------------------------------------------------------------------
// 3xBF16 tensor-core GEMM: C = A[M,1024] * B[1024,N] + bias
// mode 0: N=3072, scatter into g_q/g_k/g_v with q-scale (QKV projection)
// mode 1: N=1024, A := g_attn, plain write to out (output projection)
// BM=128, BN=64, BK=32, 256 threads (8 warps as 4m x 2n, warp tile 32x32).
// m16n8k16 bf16 mma: K=16 per instruction (2x tf32-k8) at same issue cost.
// ---------------------------------------------------------------------------
__global__ __launch_bounds__(256, 2) void gemm_tc_kernel(
    const float* __restrict__ A, const float* __restrict__ Bm,
    const float* __restrict__ bias, float* __restrict__ out,
    const int* __restrict__ lidx, int N, int mode)
{
    const int K = 1024;
    __shared__ float As[128][36];   // float2 frag loads: <=2-way (optimal)
    __shared__ float Bs[32][72];    // scalar frag loads: <=2-way

    const float* Ap = (mode == 1) ? (const float*)g_attn : A;

    int tid = threadIdx.x;
    int bm = blockIdx.y;
    int bn = blockIdx.x;
    int lane = tid & 31, warp = tid >> 5;
    int wm = (warp >> 1) * 32;      // 4 m-warps
    int wn = (warp & 1) * 32;      // 2 n-warps
    int r = lane >> 2;              // 0..7
    int c = lane & 3;               // 0..3
    int c2 = c * 2;

    const float* Ab = Ap + (size_t)bm * 128 * K;
    const float* Bb = Bm + (size_t)bn * 64;

    // gmem load assignment
    int aM = tid >> 1;              // 0..127
    int aK = (tid & 1) * 16;        // 0 or 16
    int bK = tid >> 3;              // 0..31
    int bN = (tid & 7) * 8;         // 0..56

    float acc[2][4][4];
    #pragma unroll
    for (int mi = 0; mi < 2; mi++)
        #pragma unroll
        for (int ni = 0; ni < 4; ni++)
            #pragma unroll
            for (int e = 0; e < 4; e++) acc[mi][ni][e] = 0.f;

    float4 aPref[4];
    float4 bPref[2];
    #pragma unroll
    for (int j = 0; j < 4; j++)
        aPref[j] = *(const float4*)(Ab + (size_t)aM * K + aK + j * 4);
    #pragma unroll
    for (int j = 0; j < 2; j++)
        bPref[j] = *(const float4*)(Bb + (size_t)bK * N + bN + j * 4);

    for (int k0 = 0; k0 < K; k0 += 32) {
        #pragma unroll
        for (int j = 0; j < 4; j++)
            *(float4*)&As[aM][aK + j * 4] = aPref[j];
        #pragma unroll
        for (int j = 0; j < 2; j++)
            *(float4*)&Bs[bK][bN + j * 4] = bPref[j];
        __syncthreads();

        if (k0 + 32 < K) {
            #pragma unroll
            for (int j = 0; j < 4; j++)
                aPref[j] = *(const float4*)(Ab + (size_t)aM * K + k0 + 32 + aK + j * 4);
            #pragma unroll
            for (int j = 0; j < 2; j++)
                bPref[j] = *(const float4*)(Bb + (size_t)(k0 + 32 + bK) * N + bN + j * 4);
        }

        #pragma unroll
        for (int ks = 0; ks < 2; ks++) {       // two k16 steps per 32-chunk
            int kb = ks * 16;
            // A fragments: m16k16, pairs along k -> float2 loads
            uint32_t ahi[2][4], alo[2][4];
            #pragma unroll
            for (int mi = 0; mi < 2; mi++) {
                int mrow = wm + mi * 16 + r;
                float2 p00 = *(const float2*)&As[mrow][kb + c2];
                float2 p10 = *(const float2*)&As[mrow + 8][kb + c2];
                float2 p01 = *(const float2*)&As[mrow][kb + 8 + c2];
                float2 p11 = *(const float2*)&As[mrow + 8][kb + 8 + c2];
                bsplit2(p00.x, p00.y, ahi[mi][0], alo[mi][0]);
                bsplit2(p10.x, p10.y, ahi[mi][1], alo[mi][1]);
                bsplit2(p01.x, p01.y, ahi[mi][2], alo[mi][2]);
                bsplit2(p11.x, p11.y, ahi[mi][3], alo[mi][3]);
            }
            // B fragments: k16n8, pairs along k (rows) -> scalar loads + pack
            uint32_t bhi[4][2], blo[4][2];
            #pragma unroll
            for (int ni = 0; ni < 4; ni++) {
                int ncol = wn + ni * 8 + r;
                float b00 = Bs[kb + c2][ncol];
                float b01 = Bs[kb + c2 + 1][ncol];
                float b10 = Bs[kb + 8 + c2][ncol];
                float b11 = Bs[kb + 8 + c2 + 1][ncol];
                bsplit2(b00, b01, bhi[ni][0], blo[ni][0]);
                bsplit2(b10, b11, bhi[ni][1], blo[ni][1]);
            }
            // 3-term: Ahi*Bhi + Ahi*Blo + Alo*Bhi
            #pragma unroll
            for (int mi = 0; mi < 2; mi++)
                #pragma unroll
                for (int ni = 0; ni < 4; ni++) {
                    float* d = acc[mi][ni];
                    mma_bf16(d[0], d[1], d[2], d[3],
                             ahi[mi][0], ahi[mi][1], ahi[mi][2], ahi[mi][3],
                             bhi[ni][0], bhi[ni][1]);
                    mma_bf16(d[0], d[1], d[2], d[3],
                             ahi[mi][0], ahi[mi][1], ahi[mi][2], ahi[mi][3],
                             blo[ni][0], blo[ni][1]);
                    mma_bf16(d[0], d[1], d[2], d[3],
                             alo[mi][0], alo[mi][1], alo[mi][2], alo[mi][3],
                             bhi[ni][0], bhi[ni][1]);
                }
        }
        __syncthreads();
    }

    // Epilogue. acc elem e: row = r + (e>>1)*8, col = c*2 + (e&1)
    if (mode == 0) {
        float scale = 0.125f / (float)(lidx[0] + 1);
        #pragma unroll
        for (int mi = 0; mi < 2; mi++) {
            #pragma unroll
            for (int ni = 0; ni < 4; ni++) {
                #pragma unroll
                for (int e = 0; e < 4; e++) {
                    int m = bm * 128 + wm + mi * 16 + r + (e >> 1) * 8;
                    int n = bn * 64 + wn + ni * 8 + c * 2 + (e & 1);
                    float v = acc[mi][ni][e] + bias[n];
                    int b = m >> 11, s = m & 2047;
                    int t = n >> 10;
                    int hd = n & 1023;
                    int h = hd >> 6, d = hd & 63;
                    size_t idx = ((size_t)(b * HSZ + h) * SSZ + s) * DSZ + d;
                    if (t == 0)      g_q[idx] = v * scale;
                    else if (t == 1) g_k[idx] = v;
                    else             g_v[idx] = v;
                }
            }
        }
    } else {
        #pragma unroll
        for (int mi = 0; mi < 2; mi++) {
            #pragma unroll
            for (int ni = 0; ni < 4; ni++) {
                #pragma unroll
                for (int e = 0; e < 4; e++) {
                    int m = bm * 128 + wm + mi * 16 + r + (e >> 1) * 8;
                    int n = bn * 64 + wn + ni * 8 + c * 2 + (e & 1);
                    out[(size_t)m * N + n] = acc[mi][ni][e] + bias[n];
                }
            }
        }
    }
}

// ---------------------------------------------------------------------------
// Tensor-core flash attention (unchanged from R3/R6).
// ---------------------------------------------------------------------------
__global__ __launch_bounds__(256, 1) void attn_tc_kernel()
{
    extern __shared__ float sm[];
    float (*Ks)[APAD] = (float(*)[APAD])sm;
    float (*Vs)[VPAD] = (float(*)[VPAD])(sm + 64 * APAD);
    float (*Ps)[APAD] = (float(*)[APAD])(sm + 64 * APAD + 64 * VPAD);

    int bh = blockIdx.y;
    int qb = 15 - blockIdx.x;
    int q0 = qb * 128;

    const float* qp = g_q + (size_t)bh * SSZ * DSZ + (size_t)q0 * DSZ;
    const float* kb = g_k + (size_t)bh * SSZ * DSZ;
    const float* vb = g_v + (size_t)bh * SSZ * DSZ;

    int tid = threadIdx.x, lane = tid & 31, warp = tid >> 5;
    int r = lane >> 2, c = lane & 3;
    int wr0 = warp * 16;

    {
        float (*Qs)[APAD] = (float(*)[APAD])sm;
        for (int i = tid; i < 128 * 16; i += 256) {
            int row = i >> 4, col4 = (i & 15) * 4;
            *(float4*)&Qs[row][col4] = *(const float4*)(qp + row * 64 + col4);
        }
        __syncthreads();
    }
    uint32_t qa[8][4];
    {
        float (*Qs)[APAD] = (float(*)[APAD])sm;
        #pragma unroll
        for (int ks = 0; ks < 8; ks++) {
            int k8 = ks * 8;
            qa[ks][0] = f2tf32(Qs[wr0 + r][k8 + c]);
            qa[ks][1] = f2tf32(Qs[wr0 + r + 8][k8 + c]);
            qa[ks][2] = f2tf32(Qs[wr0 + r][k8 + c + 4]);
            qa[ks][3] = f2tf32(Qs[wr0 + r + 8][k8 + c + 4]);
        }
    }

    float m0 = -1e30f, m1 = -1e30f, l0 = 0.f, l1 = 0.f;
    float o[8][4];
    #pragma unroll
    for (int ni = 0; ni < 8; ni++)
        #pragma unroll
        for (int e = 0; e < 4; e++) o[ni][e] = 0.f;

    int qrow0 = q0 + wr0 + r;
    int qrow1 = qrow0 + 8;

    int ntiles = (qb + 1) * 2;
    for (int kt = 0; kt < ntiles; kt++) {
        __syncthreads();
        const float* kp = kb + (size_t)kt * 64 * DSZ;
        const float* vp = vb + (size_t)kt * 64 * DSZ;
        for (int i = tid; i < 1024; i += 256) {
            int row = i >> 4, col4 = (i & 15) * 4;
            *(float4*)&Ks[row][col4] = *(const float4*)(kp + row * 64 + col4);
            *(float4*)&Vs[row][col4] = *(const float4*)(vp + row * 64 + col4);
        }
        __syncthreads();

        float s[8][4];
        #pragma unroll
        for (int ni = 0; ni < 8; ni++)
            #pragma unroll
            for (int e = 0; e < 4; e++) s[ni][e] = 0.f;

        #pragma unroll
        for (int ks = 0; ks < 8; ks++) {
            int k8 = ks * 8;
            #pragma unroll
            for (int ni = 0; ni < 8; ni++) {
                uint32_t b0 = f2tf32(Ks[ni * 8 + r][k8 + c]);
                uint32_t b1 = f2tf32(Ks[ni * 8 + r][k8 + c + 4]);
                mma_tf32(s[ni][0], s[ni][1], s[ni][2], s[ni][3],
                         qa[ks][0], qa[ks][1], qa[ks][2], qa[ks][3], b0, b1);
            }
        }

        if (kt * 64 + 63 > qrow0) {
            #pragma unroll
            for (int ni = 0; ni < 8; ni++) {
                int key = kt * 64 + ni * 8 + 2 * c;
                if (key     > qrow0) s[ni][0] = -1e30f;
                if (key + 1 > qrow0) s[ni][1] = -1e30f;
                if (key     > qrow1) s[ni][2] = -1e30f;
                if (key + 1 > qrow1) s[ni][3] = -1e30f;
            }
        }

        float mx0 = -1e30f, mx1 = -1e30f;
        #pragma unroll
        for (int ni = 0; ni < 8; ni++) {
            mx0 = fmaxf(mx0, fmaxf(s[ni][0], s[ni][1]));
            mx1 = fmaxf(mx1, fmaxf(s[ni][2], s[ni][3]));
        }
        mx0 = fmaxf(mx0, __shfl_xor_sync(0xffffffffu, mx0, 1));
        mx0 = fmaxf(mx0, __shfl_xor_sync(0xffffffffu, mx0, 2));
        mx1 = fmaxf(mx1, __shfl_xor_sync(0xffffffffu, mx1, 1));
        mx1 = fmaxf(mx1, __shfl_xor_sync(0xffffffffu, mx1, 2));

        float mn0 = fmaxf(m0, mx0), mn1 = fmaxf(m1, mx1);
        float sum0 = 0.f, sum1 = 0.f;
        #pragma unroll
        for (int ni = 0; ni < 8; ni++) {
            float p0 = __expf(s[ni][0] - mn0);
            float p1 = __expf(s[ni][1] - mn0);
            float p2 = __expf(s[ni][2] - mn1);
            float p3 = __expf(s[ni][3] - mn1);
            sum0 += p0 + p1;
            sum1 += p2 + p3;
            *(float2*)&Ps[wr0 + r][ni * 8 + 2 * c]     = make_float2(p0, p1);
            *(float2*)&Ps[wr0 + r + 8][ni * 8 + 2 * c] = make_float2(p2, p3);
        }
        sum0 += __shfl_xor_sync(0xffffffffu, sum0, 1);
        sum0 += __shfl_xor_sync(0xffffffffu, sum0, 2);
        sum1 += __shfl_xor_sync(0xffffffffu, sum1, 1);
        sum1 += __shfl_xor_sync(0xffffffffu, sum1, 2);

        float alpha0 = __expf(m0 - mn0);
        float alpha1 = __expf(m1 - mn1);
        l0 = l0 * alpha0 + sum0;  m0 = mn0;
        l1 = l1 * alpha1 + sum1;  m1 = mn1;
        #pragma unroll
        for (int ni = 0; ni < 8; ni++) {
            o[ni][0] *= alpha0; o[ni][1] *= alpha0;
            o[ni][2] *= alpha1; o[ni][3] *= alpha1;
        }
        __syncwarp();

        #pragma unroll
        for (int ks = 0; ks < 8; ks++) {
            int k8 = ks * 8;
            float f0 = Ps[wr0 + r][k8 + c];
            float f1 = Ps[wr0 + r + 8][k8 + c];
            float f2 = Ps[wr0 + r][k8 + c + 4];
            float f3 = Ps[wr0 + r + 8][k8 + c + 4];
            uint32_t pb0 = f2tf32(f0), pb1 = f2tf32(f1), pb2 = f2tf32(f2), pb3 = f2tf32(f3);
            uint32_t ps0 = f2tf32(f0 - __uint_as_float(pb0));
            uint32_t ps1 = f2tf32(f1 - __uint_as_float(pb1));
            uint32_t ps2 = f2tf32(f2 - __uint_as_float(pb2));
            uint32_t ps3 = f2tf32(f3 - __uint_as_float(pb3));
            #pragma unroll
            for (int ni = 0; ni < 8; ni++) {
                float v0 = Vs[k8 + c][ni * 8 + r];
                float v1 = Vs[k8 + c + 4][ni * 8 + r];
                uint32_t vb0 = f2tf32(v0), vb1 = f2tf32(v1);
                uint32_t vs0 = f2tf32(v0 - __uint_as_float(vb0));
                uint32_t vs1 = f2tf32(v1 - __uint_as_float(vb1));
                mma_tf32(o[ni][0], o[ni][1], o[ni][2], o[ni][3],
                         pb0, pb1, pb2, pb3, vb0, vb1);
                mma_tf32(o[ni][0], o[ni][1], o[ni][2], o[ni][3],
                         ps0, ps1, ps2, ps3, vb0, vb1);
                mma_tf32(o[ni][0], o[ni][1], o[ni][2], o[ni][3],
                         pb0, pb1, pb2, pb3, vs0, vs1);
            }
        }
    }

    int b = bh >> 4, h = bh & 15;
    float inv0 = 1.f / l0, inv1 = 1.f / l1;
    int s0 = q0 + wr0 + r, s1 = s0 + 8;
    size_t base0 = ((size_t)(b * SSZ + s0) * HSZ + h) * DSZ;
    size_t base1 = ((size_t)(b * SSZ + s1) * HSZ + h) * DSZ;
    #pragma unroll
    for (int ni = 0; ni < 8; ni++) {
        int d0 = ni * 8 + 2 * c;
        *(float2*)&g_attn[base0 + d0] = make_float2(o[ni][0] * inv0, o[ni][1] * inv0);
        *(float2*)&g_attn[base1 + d0] = make_float2(o[ni][2] * inv1, o[ni][3] * inv1);
    }
}

extern "C" void kernel_launch(void* const* d_in, const int* in_sizes, int n_in,
                              void* d_out, int out_size)
{
    const float* hidden = (const float*)d_in[0];
    const float* Wqkv  = (const float*)d_in[2];
    const float* bqkv  = (const float*)d_in[3];
    const float* Wproj = (const float*)d_in[4];
    const float* bproj = (const float*)d_in[5];
    const int*   lidx  = (const int*)d_in[6];
    float* out = (float*)d_out;

    int attn_smem = (64 * APAD + 64 * VPAD + 128 * APAD) * 4;
    cudaFuncSetAttribute(attn_tc_kernel,
        cudaFuncAttributeMaxDynamicSharedMemorySize, attn_smem);

    // QKV projection: M=8192, N=3072, K=1024  (BN=64 -> 48 n-blocks)
    gemm_tc_kernel<<<dim3(48, 64), 256>>>(hidden, Wqkv, bqkv, nullptr, lidx, 3072, 0);
    // Attention: 16 query tiles (128 rows each) x 64 (b,h) pairs
    attn_tc_kernel<<<dim3(16, 64), 256, attn_smem>>>();
    // Output projection: M=8192, N=1024, K=1024  (BN=64 -> 16 n-blocks)
    gemm_tc_kernel<<<dim3(16, 64), 256>>>(nullptr, Wproj, bproj, out, lidx, 1024, 1);
}

// round 9
// speedup vs baseline: 1.4665x; 1.1590x over previous
#include <cuda_runtime.h>
#include <cuda_bf16.h>
#include <math.h>
#include <stdint.h>

#define BSZ 4
#define SSZ 2048
#define ESZ 1024
#define HSZ 16
#define DSZ 64

#define APAD 68   // attn: pad for Q/K/P smem rows
#define VPAD 72   // attn: pad for V smem rows

// Scratch (allocation-free): Q/K/V laid out [B][H][S][D]; attn out [B][S][H][D]
__device__ float g_q[BSZ*HSZ*SSZ*DSZ];
__device__ float g_k[BSZ*HSZ*SSZ*DSZ];
__device__ float g_v[BSZ*HSZ*SSZ*DSZ];
__device__ float g_attn[BSZ*SSZ*HSZ*DSZ];

__device__ __forceinline__ uint32_t f2tf32(float x) {
    uint32_t r;
    asm("cvt.rna.tf32.f32 %0, %1;" : "=r"(r) : "f"(x));
    return r;
}

__device__ __forceinline__ void mma_tf32(float& d0, float& d1, float& d2, float& d3,
                                         uint32_t a0, uint32_t a1, uint32_t a2, uint32_t a3,
                                         uint32_t b0, uint32_t b1) {
    asm volatile(
        "mma.sync.aligned.m16n8k8.row.col.f32.tf32.tf32.f32 "
        "{%0,%1,%2,%3},{%4,%5,%6,%7},{%8,%9},{%0,%1,%2,%3};"
        : "+f"(d0), "+f"(d1), "+f"(d2), "+f"(d3)
        : "r"(a0), "r"(a1), "r"(a2), "r"(a3), "r"(b0), "r"(b1));
}

__device__ __forceinline__ void mma_bf16(float& d0, float& d1, float& d2, float& d3,
                                         uint32_t a0, uint32_t a1, uint32_t a2, uint32_t a3,
                                         uint32_t b0, uint32_t b1) {
    asm volatile(
        "mma.sync.aligned.m16n8k16.row.col.f32.bf16.bf16.f32 "
        "{%0,%1,%2,%3},{%4,%5,%6,%7},{%8,%9},{%0,%1,%2,%3};"
        : "+f"(d0), "+f"(d1), "+f"(d2), "+f"(d3)
        : "r"(a0), "r"(a1), "r"(a2), "r"(a3), "r"(b0), "r"(b1));
}

// Split (x0, x1) -> hi pack {bf16(x1):bf16(x0)} and lo pack of the residuals.
// Low 16 bits (lower address in smem) = first (lower-k) element.
__device__ __forceinline__ void bsplit2(float x0, float x1, uint32_t& hi, uint32_t& lo) {
    uint32_t h;
    asm("cvt.rn.bf16x2.f32 %0, %1, %2;" : "=r"(h) : "f"(x1), "f"(x0));
    float h1 = __uint_as_float(h & 0xFFFF0000u);
    float h0 = __uint_as_float(h << 16);
    float r0 = x0 - h0;
    float r1 = x1 - h1;
    asm("cvt.rn.bf16x2.f32 %0, %1, %2;" : "=r"(lo) : "f"(r1), "f"(r0));
    hi = h;
}

__device__ __forceinline__ void ldsm_x4(uint32_t& r0, uint32_t& r1, uint32_t& r2, uint32_t& r3,
                                        uint32_t addr) {
    asm volatile("ldmatrix.sync.aligned.m8n8.x4.shared.b16 {%0,%1,%2,%3}, [%4];"
        : "=r"(r0), "=r"(r1), "=r"(r2), "=r"(r3) : "r"(addr));
}
__device__ __forceinline__ void ldsm_x4_t(uint32_t& r0, uint32_t& r1, uint32_t& r2, uint32_t& r3,
                                          uint32_t addr) {
    asm volatile("ldmatrix.sync.aligned.m8n8.x4.trans.shared.b16 {%0,%1,%2,%3}, [%4];"
        : "=r"(r0), "=r"(r1), "=r"(r2), "=r"(r3) : "r"(addr));
}

// ---------------------------------------------------------------------------
// 3xBF16 tensor-core GEMM with bf16-resident smem + ldmatrix fragment loads.
// C = A[M,1024] * B[1024,N] + bias
// mode 0: N=3072, scatter into g_q/g_k/g_v with q-scale (QKV projection)
// mode 1: N=1024, A := g_attn, plain write to out (output projection)
// BM=128, BN=64, BK=32, 256 threads (8 warps as 4m x 2n, warp tile 32x32).
// Smem rows: A 40 bf16 (80B), B 72 bf16 (144B) -> LDSM conflict-free.
// ---------------------------------------------------------------------------
__global__ __launch_bounds__(256, 2) void gemm_tc_kernel(
    const float* __restrict__ A, const float* __restrict__ Bm,
    const float* __restrict__ bias, float* __restrict__ out,
    const int* __restrict__ lidx, int N, int mode)
{
    const int K = 1024;
    __shared__ __nv_bfloat16 AhiS[128][40];
    __shared__ __nv_bfloat16 AloS[128][40];
    __shared__ __nv_bfloat16 BhiS[32][72];
    __shared__ __nv_bfloat16 BloS[32][72];

    const float* Ap = (mode == 1) ? (const float*)g_attn : A;

    int tid = threadIdx.x;
    int bm = blockIdx.y;
    int bn = blockIdx.x;
    int lane = tid & 31, warp = tid >> 5;
    int wm = (warp >> 1) * 32;      // 4 m-warps
    int wn = (warp & 1) * 32;       // 2 n-warps
    int r = lane >> 2;              // 0..7
    int c = lane & 3;               // 0..3

    const float* Ab = Ap + (size_t)bm * 128 * K;
    const float* Bb = Bm + (size_t)bn * 64;

    // gmem load assignment
    int aM = tid >> 1;              // 0..127
    int aK = (tid & 1) * 16;        // 0 or 16
    int bK = tid >> 3;              // 0..31
    int bN = (tid & 7) * 8;         // 0..56

    // LDSM lane address components
    int lr   = lane & 7;
    int lm8  = (lane >> 3) & 1;     // second 8-row group (matrices 1,3)
    int lhi  = (lane >> 4) & 1;     // matrices 2,3
    uint32_t aHiB = (uint32_t)__cvta_generic_to_shared(&AhiS[0][0]);
    uint32_t aLoB = (uint32_t)__cvta_generic_to_shared(&AloS[0][0]);
    uint32_t bHiB = (uint32_t)__cvta_generic_to_shared(&BhiS[0][0]);
    uint32_t bLoB = (uint32_t)__cvta_generic_to_shared(&BloS[0][0]);
    // A: row = wm + mi*16 + lr + lm8*8 ; byte = ks*32 + lhi*16
    int aRowL = wm + lr + lm8 * 8;
    // B: krow = ks*16 + lr + lm8*8 ; byte = (wn + p*16 + lhi*8)*2
    int bRowL = lr + lm8 * 8;

    float acc[2][4][4];
    #pragma unroll
    for (int mi = 0; mi < 2; mi++)
        #pragma unroll
        for (int ni = 0; ni < 4; ni++)
            #pragma unroll
            for (int e = 0; e < 4; e++) acc[mi][ni][e] = 0.f;

    float4 aPref[4];
    float4 bPref[2];
    #pragma unroll
    for (int j = 0; j < 4; j++)
        aPref[j] = *(const float4*)(Ab + (size_t)aM * K + aK + j * 4);
    #pragma unroll
    for (int j = 0; j < 2; j++)
        bPref[j] = *(const float4*)(Bb + (size_t)bK * N + bN + j * 4);

    for (int k0 = 0; k0 < K; k0 += 32) {
        // commit: split fp32 -> bf16 hi/lo pairs, store packed
        {
            uint32_t hp[8], lp[8];
            #pragma unroll
            for (int j = 0; j < 4; j++) {
                bsplit2(aPref[j].x, aPref[j].y, hp[2*j],   lp[2*j]);
                bsplit2(aPref[j].z, aPref[j].w, hp[2*j+1], lp[2*j+1]);
            }
            *(uint4*)&AhiS[aM][aK]     = make_uint4(hp[0], hp[1], hp[2], hp[3]);
            *(uint4*)&AhiS[aM][aK + 8] = make_uint4(hp[4], hp[5], hp[6], hp[7]);
            *(uint4*)&AloS[aM][aK]     = make_uint4(lp[0], lp[1], lp[2], lp[3]);
            *(uint4*)&AloS[aM][aK + 8] = make_uint4(lp[4], lp[5], lp[6], lp[7]);

            uint32_t bh[4], bl[4];
            bsplit2(bPref[0].x, bPref[0].y, bh[0], bl[0]);
            bsplit2(bPref[0].z, bPref[0].w, bh[1], bl[1]);
            bsplit2(bPref[1].x, bPref[1].y, bh[2], bl[2]);
            bsplit2(bPref[1].z, bPref[1].w, bh[3], bl[3]);
            *(uint4*)&BhiS[bK][bN] = make_uint4(bh[0], bh[1], bh[2], bh[3]);
            *(uint4*)&BloS[bK][bN] = make_uint4(bl[0], bl[1], bl[2], bl[3]);
        }
        __syncthreads();

        if (k0 + 32 < K) {
            #pragma unroll
            for (int j = 0; j < 4; j++)
                aPref[j] = *(const float4*)(Ab + (size_t)aM * K + k0 + 32 + aK + j * 4);
            #pragma unroll
            for (int j = 0; j < 2; j++)
                bPref[j] = *(const float4*)(Bb + (size_t)(k0 + 32 + bK) * N + bN + j * 4);
        }

        #pragma unroll
        for (int ks = 0; ks < 2; ks++) {       // two k16 steps per 32-chunk
            uint32_t ahi[2][4], alo[2][4];
            #pragma unroll
            for (int mi = 0; mi < 2; mi++) {
                uint32_t off = (uint32_t)(aRowL + mi * 16) * 80u + ks * 32u + lhi * 16u;
                ldsm_x4(ahi[mi][0], ahi[mi][1], ahi[mi][2], ahi[mi][3], aHiB + off);
                ldsm_x4(alo[mi][0], alo[mi][1], alo[mi][2], alo[mi][3], aLoB + off);
            }
            uint32_t bhi[2][4], blo[2][4];     // [p]: r0,r1 = ni=2p ; r2,r3 = ni=2p+1
            #pragma unroll
            for (int p = 0; p < 2; p++) {
                uint32_t off = (uint32_t)(ks * 16 + bRowL) * 144u
                             + (uint32_t)(wn + p * 16 + lhi * 8) * 2u;
                ldsm_x4_t(bhi[p][0], bhi[p][1], bhi[p][2], bhi[p][3], bHiB + off);
                ldsm_x4_t(blo[p][0], blo[p][1], blo[p][2], blo[p][3], bLoB + off);
            }
            // 3-term: Ahi*Bhi + Ahi*Blo + Alo*Bhi
            #pragma unroll
            for (int mi = 0; mi < 2; mi++)
                #pragma unroll
                for (int p = 0; p < 2; p++)
                    #pragma unroll
                    for (int q = 0; q < 2; q++) {
                        float* d = acc[mi][2 * p + q];
                        uint32_t b0h = bhi[p][2*q], b1h = bhi[p][2*q+1];
                        uint32_t b0l = blo[p][2*q], b1l = blo[p][2*q+1];
                        mma_bf16(d[0], d[1], d[2], d[3],
                                 ahi[mi][0], ahi[mi][1], ahi[mi][2], ahi[mi][3], b0h, b1h);
                        mma_bf16(d[0], d[1], d[2], d[3],
                                 ahi[mi][0], ahi[mi][1], ahi[mi][2], ahi[mi][3], b0l, b1l);
                        mma_bf16(d[0], d[1], d[2], d[3],
                                 alo[mi][0], alo[mi][1], alo[mi][2], alo[mi][3], b0h, b1h);
                    }
        }
        __syncthreads();
    }

    // Epilogue. acc elem e: row = r + (e>>1)*8, col = c*2 + (e&1)
    if (mode == 0) {
        float scale = 0.125f / (float)(lidx[0] + 1);
        #pragma unroll
        for (int mi = 0; mi < 2; mi++) {
            #pragma unroll
            for (int ni = 0; ni < 4; ni++) {
                #pragma unroll
                for (int e = 0; e < 4; e++) {
                    int m = bm * 128 + wm + mi * 16 + r + (e >> 1) * 8;
                    int n = bn * 64 + wn + ni * 8 + c * 2 + (e & 1);
                    float v = acc[mi][ni][e] + bias[n];
                    int b = m >> 11, s = m & 2047;
                    int t = n >> 10;
                    int hd = n & 1023;
                    int h = hd >> 6, d = hd & 63;
                    size_t idx = ((size_t)(b * HSZ + h) * SSZ + s) * DSZ + d;
                    if (t == 0)      g_q[idx] = v * scale;
                    else if (t == 1) g_k[idx] = v;
                    else             g_v[idx] = v;
                }
            }
        }
    } else {
        #pragma unroll
        for (int mi = 0; mi < 2; mi++) {
            #pragma unroll
            for (int ni = 0; ni < 4; ni++) {
                #pragma unroll
                for (int e = 0; e < 4; e++) {
                    int m = bm * 128 + wm + mi * 16 + r + (e >> 1) * 8;
                    int n = bn * 64 + wn + ni * 8 + c * 2 + (e & 1);
                    out[(size_t)m * N + n] = acc[mi][ni][e] + bias[n];
                }
            }
        }
    }
}

// ---------------------------------------------------------------------------
// Tensor-core flash attention (unchanged from R3/R6/R8).
// ---------------------------------------------------------------------------
__global__ __launch_bounds__(256, 1) void attn_tc_kernel()
{
    extern __shared__ float sm[];
    float (*Ks)[APAD] = (float(*)[APAD])sm;
    float (*Vs)[VPAD] = (float(*)[VPAD])(sm + 64 * APAD);
    float (*Ps)[APAD] = (float(*)[APAD])(sm + 64 * APAD + 64 * VPAD);

    int bh = blockIdx.y;
    int qb = 15 - blockIdx.x;
    int q0 = qb * 128;

    const float* qp = g_q + (size_t)bh * SSZ * DSZ + (size_t)q0 * DSZ;
    const float* kb = g_k + (size_t)bh * SSZ * DSZ;
    const float* vb = g_v + (size_t)bh * SSZ * DSZ;

    int tid = threadIdx.x, lane = tid & 31, warp = tid >> 5;
    int r = lane >> 2, c = lane & 3;
    int wr0 = warp * 16;

    {
        float (*Qs)[APAD] = (float(*)[APAD])sm;
        for (int i = tid; i < 128 * 16; i += 256) {
            int row = i >> 4, col4 = (i & 15) * 4;
            *(float4*)&Qs[row][col4] = *(const float4*)(qp + row * 64 + col4);
        }
        __syncthreads();
    }
    uint32_t qa[8][4];
    {
        float (*Qs)[APAD] = (float(*)[APAD])sm;
        #pragma unroll
        for (int ks = 0; ks < 8; ks++) {
            int k8 = ks * 8;
            qa[ks][0] = f2tf32(Qs[wr0 + r][k8 + c]);
            qa[ks][1] = f2tf32(Qs[wr0 + r + 8][k8 + c]);
            qa[ks][2] = f2tf32(Qs[wr0 + r][k8 + c + 4]);
            qa[ks][3] = f2tf32(Qs[wr0 + r + 8][k8 + c + 4]);
        }
    }

    float m0 = -1e30f, m1 = -1e30f, l0 = 0.f, l1 = 0.f;
    float o[8][4];
    #pragma unroll
    for (int ni = 0; ni < 8; ni++)
        #pragma unroll
        for (int e = 0; e < 4; e++) o[ni][e] = 0.f;

    int qrow0 = q0 + wr0 + r;
    int qrow1 = qrow0 + 8;

    int ntiles = (qb + 1) * 2;
    for (int kt = 0; kt < ntiles; kt++) {
        __syncthreads();
        const float* kp = kb + (size_t)kt * 64 * DSZ;
        const float* vp = vb + (size_t)kt * 64 * DSZ;
        for (int i = tid; i < 1024; i += 256) {
            int row = i >> 4, col4 = (i & 15) * 4;
            *(float4*)&Ks[row][col4] = *(const float4*)(kp + row * 64 + col4);
            *(float4*)&Vs[row][col4] = *(const float4*)(vp + row * 64 + col4);
        }
        __syncthreads();

        float s[8][4];
        #pragma unroll
        for (int ni = 0; ni < 8; ni++)
            #pragma unroll
            for (int e = 0; e < 4; e++) s[ni][e] = 0.f;

        #pragma unroll
        for (int ks = 0; ks < 8; ks++) {
            int k8 = ks * 8;
            #pragma unroll
            for (int ni = 0; ni < 8; ni++) {
                uint32_t b0 = f2tf32(Ks[ni * 8 + r][k8 + c]);
                uint32_t b1 = f2tf32(Ks[ni * 8 + r][k8 + c + 4]);
                mma_tf32(s[ni][0], s[ni][1], s[ni][2], s[ni][3],
                         qa[ks][0], qa[ks][1], qa[ks][2], qa[ks][3], b0, b1);
            }
        }

        if (kt * 64 + 63 > qrow0) {
            #pragma unroll
            for (int ni = 0; ni < 8; ni++) {
                int key = kt * 64 + ni * 8 + 2 * c;
                if (key     > qrow0) s[ni][0] = -1e30f;
                if (key + 1 > qrow0) s[ni][1] = -1e30f;
                if (key     > qrow1) s[ni][2] = -1e30f;
                if (key + 1 > qrow1) s[ni][3] = -1e30f;
            }
        }

        float mx0 = -1e30f, mx1 = -1e30f;
        #pragma unroll
        for (int ni = 0; ni < 8; ni++) {
            mx0 = fmaxf(mx0, fmaxf(s[ni][0], s[ni][1]));
            mx1 = fmaxf(mx1, fmaxf(s[ni][2], s[ni][3]));
        }
        mx0 = fmaxf(mx0, __shfl_xor_sync(0xffffffffu, mx0, 1));
        mx0 = fmaxf(mx0, __shfl_xor_sync(0xffffffffu, mx0, 2));
        mx1 = fmaxf(mx1, __shfl_xor_sync(0xffffffffu, mx1, 1));
        mx1 = fmaxf(mx1, __shfl_xor_sync(0xffffffffu, mx1, 2));

        float mn0 = fmaxf(m0, mx0), mn1 = fmaxf(m1, mx1);
        float sum0 = 0.f, sum1 = 0.f;
        #pragma unroll
        for (int ni = 0; ni < 8; ni++) {
            float p0 = __expf(s[ni][0] - mn0);
            float p1 = __expf(s[ni][1] - mn0);
            float p2 = __expf(s[ni][2] - mn1);
            float p3 = __expf(s[ni][3] - mn1);
            sum0 += p0 + p1;
            sum1 += p2 + p3;
            *(float2*)&Ps[wr0 + r][ni * 8 + 2 * c]     = make_float2(p0, p1);
            *(float2*)&Ps[wr0 + r + 8][ni * 8 + 2 * c] = make_float2(p2, p3);
        }
        sum0 += __shfl_xor_sync(0xffffffffu, sum0, 1);
        sum0 += __shfl_xor_sync(0xffffffffu, sum0, 2);
        sum1 += __shfl_xor_sync(0xffffffffu, sum1, 1);
        sum1 += __shfl_xor_sync(0xffffffffu, sum1, 2);

        float alpha0 = __expf(m0 - mn0);
        float alpha1 = __expf(m1 - mn1);
        l0 = l0 * alpha0 + sum0;  m0 = mn0;
        l1 = l1 * alpha1 + sum1;  m1 = mn1;
        #pragma unroll
        for (int ni = 0; ni < 8; ni++) {
            o[ni][0] *= alpha0; o[ni][1] *= alpha0;
            o[ni][2] *= alpha1; o[ni][3] *= alpha1;
        }
        __syncwarp();

        #pragma unroll
        for (int ks = 0; ks < 8; ks++) {
            int k8 = ks * 8;
            float f0 = Ps[wr0 + r][k8 + c];
            float f1 = Ps[wr0 + r + 8][k8 + c];
            float f2 = Ps[wr0 + r][k8 + c + 4];
            float f3 = Ps[wr0 + r + 8][k8 + c + 4];
            uint32_t pb0 = f2tf32(f0), pb1 = f2tf32(f1), pb2 = f2tf32(f2), pb3 = f2tf32(f3);
            uint32_t ps0 = f2tf32(f0 - __uint_as_float(pb0));
            uint32_t ps1 = f2tf32(f1 - __uint_as_float(pb1));
            uint32_t ps2 = f2tf32(f2 - __uint_as_float(pb2));
            uint32_t ps3 = f2tf32(f3 - __uint_as_float(pb3));
            #pragma unroll
            for (int ni = 0; ni < 8; ni++) {
                float v0 = Vs[k8 + c][ni * 8 + r];
                float v1 = Vs[k8 + c + 4][ni * 8 + r];
                uint32_t vb0 = f2tf32(v0), vb1 = f2tf32(v1);
                uint32_t vs0 = f2tf32(v0 - __uint_as_float(vb0));
                uint32_t vs1 = f2tf32(v1 - __uint_as_float(vb1));
                mma_tf32(o[ni][0], o[ni][1], o[ni][2], o[ni][3],
                         pb0, pb1, pb2, pb3, vb0, vb1);
                mma_tf32(o[ni][0], o[ni][1], o[ni][2], o[ni][3],
                         ps0, ps1, ps2, ps3, vb0, vb1);
                mma_tf32(o[ni][0], o[ni][1], o[ni][2], o[ni][3],
                         pb0, pb1, pb2, pb3, vs0, vs1);
            }
        }
    }

    int b = bh >> 4, h = bh & 15;
    float inv0 = 1.f / l0, inv1 = 1.f / l1;
    int s0 = q0 + wr0 + r, s1 = s0 + 8;
    size_t base0 = ((size_t)(b * SSZ + s0) * HSZ + h) * DSZ;
    size_t base1 = ((size_t)(b * SSZ + s1) * HSZ + h) * DSZ;
    #pragma unroll
    for (int ni = 0; ni < 8; ni++) {
        int d0 = ni * 8 + 2 * c;
        *(float2*)&g_attn[base0 + d0] = make_float2(o[ni][0] * inv0, o[ni][1] * inv0);
        *(float2*)&g_attn[base1 + d0] = make_float2(o[ni][2] * inv1, o[ni][3] * inv1);
    }
}

extern "C" void kernel_launch(void* const* d_in, const int* in_sizes, int n_in,
                              void* d_out, int out_size)
{
    const float* hidden = (const float*)d_in[0];
    const float* Wqkv  = (const float*)d_in[2];
    const float* bqkv  = (const float*)d_in[3];
    const float* Wproj = (const float*)d_in[4];
    const float* bproj = (const float*)d_in[5];
    const int*   lidx  = (const int*)d_in[6];
    float* out = (float*)d_out;

    int attn_smem = (64 * APAD + 64 * VPAD + 128 * APAD) * 4;
    cudaFuncSetAttribute(attn_tc_kernel,
        cudaFuncAttributeMaxDynamicSharedMemorySize, attn_smem);

    // QKV projection: M=8192, N=3072, K=1024  (BN=64 -> 48 n-blocks)
    gemm_tc_kernel<<<dim3(48, 64), 256>>>(hidden, Wqkv, bqkv, nullptr, lidx, 3072, 0);
    // Attention: 16 query tiles (128 rows each) x 64 (b,h) pairs
    attn_tc_kernel<<<dim3(16, 64), 256, attn_smem>>>();
    // Output projection: M=8192, N=1024, K=1024  (BN=64 -> 16 n-blocks)
    gemm_tc_kernel<<<dim3(16, 64), 256>>>(nullptr, Wproj, bproj, out, lidx, 1024, 1);
}

// round 10
// speedup vs baseline: 1.6905x; 1.1528x over previous
#include <cuda_runtime.h>
#include <cuda_bf16.h>
#include <math.h>
#include <stdint.h>

#define BSZ 4
#define SSZ 2048
#define ESZ 1024
#define HSZ 16
#define DSZ 64

#define QPAD 68    // attn: Q staging stride (fp32)
#define KPADF 68   // attn: K smem stride (fp32/tf32 words)
#define PPADB 72   // attn: P smem stride (bf16)
#define VPADB 72   // attn: V smem stride (bf16)

// Scratch (allocation-free): Q/K/V laid out [B][H][S][D]; attn out [B][S][H][D]
__device__ float g_q[BSZ*HSZ*SSZ*DSZ];
__device__ float g_k[BSZ*HSZ*SSZ*DSZ];
__device__ float g_v[BSZ*HSZ*SSZ*DSZ];
__device__ float g_attn[BSZ*SSZ*HSZ*DSZ];

__device__ __forceinline__ uint32_t f2tf32(float x) {
    uint32_t r;
    asm("cvt.rna.tf32.f32 %0, %1;" : "=r"(r) : "f"(x));
    return r;
}

__device__ __forceinline__ void mma_tf32(float& d0, float& d1, float& d2, float& d3,
                                         uint32_t a0, uint32_t a1, uint32_t a2, uint32_t a3,
                                         uint32_t b0, uint32_t b1) {
    asm volatile(
        "mma.sync.aligned.m16n8k8.row.col.f32.tf32.tf32.f32 "
        "{%0,%1,%2,%3},{%4,%5,%6,%7},{%8,%9},{%0,%1,%2,%3};"
        : "+f"(d0), "+f"(d1), "+f"(d2), "+f"(d3)
        : "r"(a0), "r"(a1), "r"(a2), "r"(a3), "r"(b0), "r"(b1));
}

__device__ __forceinline__ void mma_bf16(float& d0, float& d1, float& d2, float& d3,
                                         uint32_t a0, uint32_t a1, uint32_t a2, uint32_t a3,
                                         uint32_t b0, uint32_t b1) {
    asm volatile(
        "mma.sync.aligned.m16n8k16.row.col.f32.bf16.bf16.f32 "
        "{%0,%1,%2,%3},{%4,%5,%6,%7},{%8,%9},{%0,%1,%2,%3};"
        : "+f"(d0), "+f"(d1), "+f"(d2), "+f"(d3)
        : "r"(a0), "r"(a1), "r"(a2), "r"(a3), "r"(b0), "r"(b1));
}

// Split (x0, x1) -> hi pack {bf16(x1):bf16(x0)} and lo pack of the residuals.
// Low 16 bits (lower address in smem) = first element.
__device__ __forceinline__ void bsplit2(float x0, float x1, uint32_t& hi, uint32_t& lo) {
    uint32_t h;
    asm("cvt.rn.bf16x2.f32 %0, %1, %2;" : "=r"(h) : "f"(x1), "f"(x0));
    float h1 = __uint_as_float(h & 0xFFFF0000u);
    float h0 = __uint_as_float(h << 16);
    float r0 = x0 - h0;
    float r1 = x1 - h1;
    asm("cvt.rn.bf16x2.f32 %0, %1, %2;" : "=r"(lo) : "f"(r1), "f"(r0));
    hi = h;
}

__device__ __forceinline__ void ldsm_x4(uint32_t& r0, uint32_t& r1, uint32_t& r2, uint32_t& r3,
                                        uint32_t addr) {
    asm volatile("ldmatrix.sync.aligned.m8n8.x4.shared.b16 {%0,%1,%2,%3}, [%4];"
        : "=r"(r0), "=r"(r1), "=r"(r2), "=r"(r3) : "r"(addr));
}
__device__ __forceinline__ void ldsm_x4_t(uint32_t& r0, uint32_t& r1, uint32_t& r2, uint32_t& r3,
                                          uint32_t addr) {
    asm volatile("ldmatrix.sync.aligned.m8n8.x4.trans.shared.b16 {%0,%1,%2,%3}, [%4];"
        : "=r"(r0), "=r"(r1), "=r"(r2), "=r"(r3) : "r"(addr));
}

// ---------------------------------------------------------------------------
// 3xBF16 tensor-core GEMM with bf16-resident smem + ldmatrix (unchanged R9).
// ---------------------------------------------------------------------------
__global__ __launch_bounds__(256, 2) void gemm_tc_kernel(
    const float* __restrict__ A, const float* __restrict__ Bm,
    const float* __restrict__ bias, float* __restrict__ out,
    const int* __restrict__ lidx, int N, int mode)
{
    const int K = 1024;
    __shared__ __nv_bfloat16 AhiS[128][40];
    __shared__ __nv_bfloat16 AloS[128][40];
    __shared__ __nv_bfloat16 BhiS[32][72];
    __shared__ __nv_bfloat16 BloS[32][72];

    const float* Ap = (mode == 1) ? (const float*)g_attn : A;

    int tid = threadIdx.x;
    int bm = blockIdx.y;
    int bn = blockIdx.x;
    int lane = tid & 31, warp = tid >> 5;
    int wm = (warp >> 1) * 32;
    int wn = (warp & 1) * 32;
    int r = lane >> 2;
    int c = lane & 3;

    const float* Ab = Ap + (size_t)bm * 128 * K;
    const float* Bb = Bm + (size_t)bn * 64;

    int aM = tid >> 1;
    int aK = (tid & 1) * 16;
    int bK = tid >> 3;
    int bN = (tid & 7) * 8;

    int lr   = lane & 7;
    int lm8  = (lane >> 3) & 1;
    int lhi  = (lane >> 4) & 1;
    uint32_t aHiB = (uint32_t)__cvta_generic_to_shared(&AhiS[0][0]);
    uint32_t aLoB = (uint32_t)__cvta_generic_to_shared(&AloS[0][0]);
    uint32_t bHiB = (uint32_t)__cvta_generic_to_shared(&BhiS[0][0]);
    uint32_t bLoB = (uint32_t)__cvta_generic_to_shared(&BloS[0][0]);
    int aRowL = wm + lr + lm8 * 8;
    int bRowL = lr + lm8 * 8;

    float acc[2][4][4];
    #pragma unroll
    for (int mi = 0; mi < 2; mi++)
        #pragma unroll
        for (int ni = 0; ni < 4; ni++)
            #pragma unroll
            for (int e = 0; e < 4; e++) acc[mi][ni][e] = 0.f;

    float4 aPref[4];
    float4 bPref[2];
    #pragma unroll
    for (int j = 0; j < 4; j++)
        aPref[j] = *(const float4*)(Ab + (size_t)aM * K + aK + j * 4);
    #pragma unroll
    for (int j = 0; j < 2; j++)
        bPref[j] = *(const float4*)(Bb + (size_t)bK * N + bN + j * 4);

    for (int k0 = 0; k0 < K; k0 += 32) {
        {
            uint32_t hp[8], lp[8];
            #pragma unroll
            for (int j = 0; j < 4; j++) {
                bsplit2(aPref[j].x, aPref[j].y, hp[2*j],   lp[2*j]);
                bsplit2(aPref[j].z, aPref[j].w, hp[2*j+1], lp[2*j+1]);
            }
            *(uint4*)&AhiS[aM][aK]     = make_uint4(hp[0], hp[1], hp[2], hp[3]);
            *(uint4*)&AhiS[aM][aK + 8] = make_uint4(hp[4], hp[5], hp[6], hp[7]);
            *(uint4*)&AloS[aM][aK]     = make_uint4(lp[0], lp[1], lp[2], lp[3]);
            *(uint4*)&AloS[aM][aK + 8] = make_uint4(lp[4], lp[5], lp[6], lp[7]);

            uint32_t bh[4], bl[4];
            bsplit2(bPref[0].x, bPref[0].y, bh[0], bl[0]);
            bsplit2(bPref[0].z, bPref[0].w, bh[1], bl[1]);
            bsplit2(bPref[1].x, bPref[1].y, bh[2], bl[2]);
            bsplit2(bPref[1].z, bPref[1].w, bh[3], bl[3]);
            *(uint4*)&BhiS[bK][bN] = make_uint4(bh[0], bh[1], bh[2], bh[3]);
            *(uint4*)&BloS[bK][bN] = make_uint4(bl[0], bl[1], bl[2], bl[3]);
        }
        __syncthreads();

        if (k0 + 32 < K) {
            #pragma unroll
            for (int j = 0; j < 4; j++)
                aPref[j] = *(const float4*)(Ab + (size_t)aM * K + k0 + 32 + aK + j * 4);
            #pragma unroll
            for (int j = 0; j < 2; j++)
                bPref[j] = *(const float4*)(Bb + (size_t)(k0 + 32 + bK) * N + bN + j * 4);
        }

        #pragma unroll
        for (int ks = 0; ks < 2; ks++) {
            uint32_t ahi[2][4], alo[2][4];
            #pragma unroll
            for (int mi = 0; mi < 2; mi++) {
                uint32_t off = (uint32_t)(aRowL + mi * 16) * 80u + ks * 32u + lhi * 16u;
                ldsm_x4(ahi[mi][0], ahi[mi][1], ahi[mi][2], ahi[mi][3], aHiB + off);
                ldsm_x4(alo[mi][0], alo[mi][1], alo[mi][2], alo[mi][3], aLoB + off);
            }
            uint32_t bhi[2][4], blo[2][4];
            #pragma unroll
            for (int p = 0; p < 2; p++) {
                uint32_t off = (uint32_t)(ks * 16 + bRowL) * 144u
                             + (uint32_t)(wn + p * 16 + lhi * 8) * 2u;
                ldsm_x4_t(bhi[p][0], bhi[p][1], bhi[p][2], bhi[p][3], bHiB + off);
                ldsm_x4_t(blo[p][0], blo[p][1], blo[p][2], blo[p][3], bLoB + off);
            }
            #pragma unroll
            for (int mi = 0; mi < 2; mi++)
                #pragma unroll
                for (int p = 0; p < 2; p++)
                    #pragma unroll
                    for (int q = 0; q < 2; q++) {
                        float* d = acc[mi][2 * p + q];
                        uint32_t b0h = bhi[p][2*q], b1h = bhi[p][2*q+1];
                        uint32_t b0l = blo[p][2*q], b1l = blo[p][2*q+1];
                        mma_bf16(d[0], d[1], d[2], d[3],
                                 ahi[mi][0], ahi[mi][1], ahi[mi][2], ahi[mi][3], b0h, b1h);
                        mma_bf16(d[0], d[1], d[2], d[3],
                                 ahi[mi][0], ahi[mi][1], ahi[mi][2], ahi[mi][3], b0l, b1l);
                        mma_bf16(d[0], d[1], d[2], d[3],
                                 alo[mi][0], alo[mi][1], alo[mi][2], alo[mi][3], b0h, b1h);
                    }
        }
        __syncthreads();
    }

    if (mode == 0) {
        float scale = 0.125f / (float)(lidx[0] + 1);
        #pragma unroll
        for (int mi = 0; mi < 2; mi++) {
            #pragma unroll
            for (int ni = 0; ni < 4; ni++) {
                #pragma unroll
                for (int e = 0; e < 4; e++) {
                    int m = bm * 128 + wm + mi * 16 + r + (e >> 1) * 8;
                    int n = bn * 64 + wn + ni * 8 + c * 2 + (e & 1);
                    float v = acc[mi][ni][e] + bias[n];
                    int b = m >> 11, s = m & 2047;
                    int t = n >> 10;
                    int hd = n & 1023;
                    int h = hd >> 6, d = hd & 63;
                    size_t idx = ((size_t)(b * HSZ + h) * SSZ + s) * DSZ + d;
                    if (t == 0)      g_q[idx] = v * scale;
                    else if (t == 1) g_k[idx] = v;
                    else             g_v[idx] = v;
                }
            }
        }
    } else {
        #pragma unroll
        for (int mi = 0; mi < 2; mi++) {
            #pragma unroll
            for (int ni = 0; ni < 4; ni++) {
                #pragma unroll
                for (int e = 0; e < 4; e++) {
                    int m = bm * 128 + wm + mi * 16 + r + (e >> 1) * 8;
                    int n = bn * 64 + wn + ni * 8 + c * 2 + (e & 1);
                    out[(size_t)m * N + n] = acc[mi][ni][e] + bias[n];
                }
            }
        }
    }
}

// ---------------------------------------------------------------------------
// Tensor-core flash attention, R10: tf32-at-commit K + ldmatrix QK frags;
// 3xBF16 k16 PV with bf16 hi/lo V (commit-time) and P (store-time), ldmatrix.
// Block = 128 q-rows of one (b,h); 8 warps x 16 rows.
// Smem: Ks[64][68] tf32 (17408B) | Vhi/Vlo[64][72] bf16 (9216B ea)
//       | Phi/Plo[128][72] bf16 (18432B ea)  -> 72704 B total.
// ---------------------------------------------------------------------------
__global__ __launch_bounds__(256, 1) void attn_tc_kernel()
{
    extern __shared__ char smc[];
    uint32_t* KsW = (uint32_t*)smc;                         // [64][68] tf32 bits
    char* VhiC = smc + 17408;                               // [64][72] bf16
    char* VloC = smc + 26624;
    char* PhiC = smc + 35840;                               // [128][72] bf16
    char* PloC = smc + 54272;

    uint32_t ksB  = (uint32_t)__cvta_generic_to_shared(KsW);
    uint32_t vhiB = (uint32_t)__cvta_generic_to_shared(VhiC);
    uint32_t vloB = (uint32_t)__cvta_generic_to_shared(VloC);
    uint32_t phiB = (uint32_t)__cvta_generic_to_shared(PhiC);
    uint32_t ploB = (uint32_t)__cvta_generic_to_shared(PloC);

    int bh = blockIdx.y;
    int qb = 15 - blockIdx.x;
    int q0 = qb * 128;

    const float* qp = g_q + (size_t)bh * SSZ * DSZ + (size_t)q0 * DSZ;
    const float* kb = g_k + (size_t)bh * SSZ * DSZ;
    const float* vb = g_v + (size_t)bh * SSZ * DSZ;

    int tid = threadIdx.x, lane = tid & 31, warp = tid >> 5;
    int r = lane >> 2, c = lane & 3;
    int wr0 = warp * 16;
    int lr  = lane & 7;
    int lm8 = (lane >> 3) & 1;
    int lhi = (lane >> 4) & 1;
    // K-ldsm group decode: g = lane>>3 -> (dn, dk)
    int g   = lane >> 3;
    int kdn = (g & 1) * 8;
    int kdk = (g >> 1) * 4;

    // Phase 1: Q -> smem -> tf32 A-frags in registers (held all kernel)
    {
        float (*Qs)[QPAD] = (float(*)[QPAD])smc;
        for (int i = tid; i < 128 * 16; i += 256) {
            int row = i >> 4, col4 = (i & 15) * 4;
            *(float4*)&Qs[row][col4] = *(const float4*)(qp + row * 64 + col4);
        }
        __syncthreads();
    }
    uint32_t qa[8][4];
    {
        float (*Qs)[QPAD] = (float(*)[QPAD])smc;
        #pragma unroll
        for (int ks = 0; ks < 8; ks++) {
            int k8 = ks * 8;
            qa[ks][0] = f2tf32(Qs[wr0 + r][k8 + c]);
            qa[ks][1] = f2tf32(Qs[wr0 + r + 8][k8 + c]);
            qa[ks][2] = f2tf32(Qs[wr0 + r][k8 + c + 4]);
            qa[ks][3] = f2tf32(Qs[wr0 + r + 8][k8 + c + 4]);
        }
    }

    float m0 = -1e30f, m1 = -1e30f, l0 = 0.f, l1 = 0.f;
    float o[8][4];
    #pragma unroll
    for (int ni = 0; ni < 8; ni++)
        #pragma unroll
        for (int e = 0; e < 4; e++) o[ni][e] = 0.f;

    int qrow0 = q0 + wr0 + r;
    int qrow1 = qrow0 + 8;

    int ntiles = (qb + 1) * 2;
    for (int kt = 0; kt < ntiles; kt++) {
        __syncthreads();   // prior PV ldsm done; Q phase done (first iter)
        const float* kp = kb + (size_t)kt * 64 * DSZ;
        const float* vp = vb + (size_t)kt * 64 * DSZ;
        // Commit K (tf32) and V (bf16 hi/lo)
        for (int i = tid; i < 1024; i += 256) {
            int row = i >> 4, col4 = (i & 15) * 4;
            float4 k4 = *(const float4*)(kp + row * 64 + col4);
            uint4 kt4;
            kt4.x = f2tf32(k4.x); kt4.y = f2tf32(k4.y);
            kt4.z = f2tf32(k4.z); kt4.w = f2tf32(k4.w);
            *(uint4*)&KsW[row * KPADF + col4] = kt4;

            float4 v4 = *(const float4*)(vp + row * 64 + col4);
            uint32_t h0, l0r, h1, l1r;
            bsplit2(v4.x, v4.y, h0, l0r);
            bsplit2(v4.z, v4.w, h1, l1r);
            *(uint2*)(VhiC + row * (VPADB*2) + col4 * 2) = make_uint2(h0, h1);
            *(uint2*)(VloC + row * (VPADB*2) + col4 * 2) = make_uint2(l0r, l1r);
        }
        __syncthreads();

        // QK^T via ldmatrix tf32 B-frags (single-pass tf32)
        float s[8][4];
        #pragma unroll
        for (int ni = 0; ni < 8; ni++)
            #pragma unroll
            for (int e = 0; e < 4; e++) s[ni][e] = 0.f;

        #pragma unroll
        for (int ks = 0; ks < 8; ks++) {
            int k8 = ks * 8;
            #pragma unroll
            for (int np = 0; np < 4; np++) {
                uint32_t kb0, kb1, kb2, kb3;
                uint32_t off = (uint32_t)((np * 16 + kdn + lr) * KPADF + k8 + kdk) * 4u;
                ldsm_x4(kb0, kb1, kb2, kb3, ksB + off);
                mma_tf32(s[2*np][0], s[2*np][1], s[2*np][2], s[2*np][3],
                         qa[ks][0], qa[ks][1], qa[ks][2], qa[ks][3], kb0, kb2);
                mma_tf32(s[2*np+1][0], s[2*np+1][1], s[2*np+1][2], s[2*np+1][3],
                         qa[ks][0], qa[ks][1], qa[ks][2], qa[ks][3], kb1, kb3);
            }
        }

        // causal mask
        if (kt * 64 + 63 > qrow0) {
            #pragma unroll
            for (int ni = 0; ni < 8; ni++) {
                int key = kt * 64 + ni * 8 + 2 * c;
                if (key     > qrow0) s[ni][0] = -1e30f;
                if (key + 1 > qrow0) s[ni][1] = -1e30f;
                if (key     > qrow1) s[ni][2] = -1e30f;
                if (key + 1 > qrow1) s[ni][3] = -1e30f;
            }
        }

        // online softmax (registers + quad shfl)
        float mx0 = -1e30f, mx1 = -1e30f;
        #pragma unroll
        for (int ni = 0; ni < 8; ni++) {
            mx0 = fmaxf(mx0, fmaxf(s[ni][0], s[ni][1]));
            mx1 = fmaxf(mx1, fmaxf(s[ni][2], s[ni][3]));
        }
        mx0 = fmaxf(mx0, __shfl_xor_sync(0xffffffffu, mx0, 1));
        mx0 = fmaxf(mx0, __shfl_xor_sync(0xffffffffu, mx0, 2));
        mx1 = fmaxf(mx1, __shfl_xor_sync(0xffffffffu, mx1, 1));
        mx1 = fmaxf(mx1, __shfl_xor_sync(0xffffffffu, mx1, 2));

        float mn0 = fmaxf(m0, mx0), mn1 = fmaxf(m1, mx1);
        float sum0 = 0.f, sum1 = 0.f;
        #pragma unroll
        for (int ni = 0; ni < 8; ni++) {
            float p0 = __expf(s[ni][0] - mn0);
            float p1 = __expf(s[ni][1] - mn0);
            float p2 = __expf(s[ni][2] - mn1);
            float p3 = __expf(s[ni][3] - mn1);
            sum0 += p0 + p1;
            sum1 += p2 + p3;
            // store P as bf16 hi/lo packs: rows wr0+r and wr0+r+8, cols ni*8+2c..+1
            uint32_t h, lw;
            int byte0 = (wr0 + r) * (PPADB*2) + (ni * 8 + 2 * c) * 2;
            int byte1 = (wr0 + r + 8) * (PPADB*2) + (ni * 8 + 2 * c) * 2;
            bsplit2(p0, p1, h, lw);
            *(uint32_t*)(PhiC + byte0) = h;
            *(uint32_t*)(PloC + byte0) = lw;
            bsplit2(p2, p3, h, lw);
            *(uint32_t*)(PhiC + byte1) = h;
            *(uint32_t*)(PloC + byte1) = lw;
        }
        sum0 += __shfl_xor_sync(0xffffffffu, sum0, 1);
        sum0 += __shfl_xor_sync(0xffffffffu, sum0, 2);
        sum1 += __shfl_xor_sync(0xffffffffu, sum1, 1);
        sum1 += __shfl_xor_sync(0xffffffffu, sum1, 2);

        float alpha0 = __expf(m0 - mn0);
        float alpha1 = __expf(m1 - mn1);
        l0 = l0 * alpha0 + sum0;  m0 = mn0;
        l1 = l1 * alpha1 + sum1;  m1 = mn1;
        #pragma unroll
        for (int ni = 0; ni < 8; ni++) {
            o[ni][0] *= alpha0; o[ni][1] *= alpha0;
            o[ni][2] *= alpha1; o[ni][3] *= alpha1;
        }
        __syncwarp();   // P rows are warp-private

        // PV: O += P * V, 3xBF16 k16 via ldmatrix
        #pragma unroll
        for (int ks = 0; ks < 4; ks++) {
            uint32_t phf[4], plf[4];
            uint32_t offP = (uint32_t)(wr0 + lr + lm8 * 8) * (PPADB*2)
                          + (uint32_t)(ks * 16 + lhi * 8) * 2u;
            ldsm_x4(phf[0], phf[1], phf[2], phf[3], phiB + offP);
            ldsm_x4(plf[0], plf[1], plf[2], plf[3], ploB + offP);

            uint32_t vhf[4][4], vlf[4][4];
            #pragma unroll
            for (int p = 0; p < 4; p++) {
                uint32_t offV = (uint32_t)(ks * 16 + lr + lm8 * 8) * (VPADB*2)
                              + (uint32_t)(p * 16 + lhi * 8) * 2u;
                ldsm_x4_t(vhf[p][0], vhf[p][1], vhf[p][2], vhf[p][3], vhiB + offV);
                ldsm_x4_t(vlf[p][0], vlf[p][1], vlf[p][2], vlf[p][3], vloB + offV);
            }
            #pragma unroll
            for (int p = 0; p < 4; p++)
                #pragma unroll
                for (int q = 0; q < 2; q++) {
                    float* d = o[2 * p + q];
                    uint32_t b0h = vhf[p][2*q], b1h = vhf[p][2*q+1];
                    uint32_t b0l = vlf[p][2*q], b1l = vlf[p][2*q+1];
                    mma_bf16(d[0], d[1], d[2], d[3],
                             phf[0], phf[1], phf[2], phf[3], b0h, b1h);
                    mma_bf16(d[0], d[1], d[2], d[3],
                             phf[0], phf[1], phf[2], phf[3], b0l, b1l);
                    mma_bf16(d[0], d[1], d[2], d[3],
                             plf[0], plf[1], plf[2], plf[3], b0h, b1h);
                }
        }
    }

    // Epilogue: normalize and write [B][S][H][D]
    int b = bh >> 4, h = bh & 15;
    float inv0 = 1.f / l0, inv1 = 1.f / l1;
    int s0 = q0 + wr0 + r, s1 = s0 + 8;
    size_t base0 = ((size_t)(b * SSZ + s0) * HSZ + h) * DSZ;
    size_t base1 = ((size_t)(b * SSZ + s1) * HSZ + h) * DSZ;
    #pragma unroll
    for (int ni = 0; ni < 8; ni++) {
        int d0 = ni * 8 + 2 * c;
        *(float2*)&g_attn[base0 + d0] = make_float2(o[ni][0] * inv0, o[ni][1] * inv0);
        *(float2*)&g_attn[base1 + d0] = make_float2(o[ni][2] * inv1, o[ni][3] * inv1);
    }
}

extern "C" void kernel_launch(void* const* d_in, const int* in_sizes, int n_in,
                              void* d_out, int out_size)
{
    const float* hidden = (const float*)d_in[0];
    const float* Wqkv  = (const float*)d_in[2];
    const float* bqkv  = (const float*)d_in[3];
    const float* Wproj = (const float*)d_in[4];
    const float* bproj = (const float*)d_in[5];
    const int*   lidx  = (const int*)d_in[6];
    float* out = (float*)d_out;

    const int attn_smem = 72704;
    cudaFuncSetAttribute(attn_tc_kernel,
        cudaFuncAttributeMaxDynamicSharedMemorySize, attn_smem);

    // QKV projection: M=8192, N=3072, K=1024
    gemm_tc_kernel<<<dim3(48, 64), 256>>>(hidden, Wqkv, bqkv, nullptr, lidx, 3072, 0);
    // Attention: 16 query tiles (128 rows each) x 64 (b,h) pairs
    attn_tc_kernel<<<dim3(16, 64), 256, attn_smem>>>();
    // Output projection: M=8192, N=1024, K=1024
    gemm_tc_kernel<<<dim3(16, 64), 256>>>(nullptr, Wproj, bproj, out, lidx, 1024, 1);
}

// round 11
// speedup vs baseline: 1.7850x; 1.0558x over previous
#include <cuda_runtime.h>
#include <cuda_bf16.h>
#include <math.h>
#include <stdint.h>

#define BSZ 4
#define SSZ 2048
#define ESZ 1024
#define HSZ 16
#define DSZ 64

#define QPAD 68    // attn: Q staging stride (fp32)
#define KPADF 68   // attn: K smem stride (fp32/tf32 words)
#define PPADB 72   // attn: P smem stride (bf16)
#define VPADB 72   // attn: V smem stride (bf16)

// Scratch (allocation-free): Q/K/V laid out [B][H][S][D]; attn out [B][S][H][D]
__device__ float g_q[BSZ*HSZ*SSZ*DSZ];
__device__ float g_k[BSZ*HSZ*SSZ*DSZ];
__device__ float g_v[BSZ*HSZ*SSZ*DSZ];
__device__ float g_attn[BSZ*SSZ*HSZ*DSZ];

__device__ __forceinline__ uint32_t f2tf32(float x) {
    uint32_t r;
    asm("cvt.rna.tf32.f32 %0, %1;" : "=r"(r) : "f"(x));
    return r;
}

__device__ __forceinline__ void mma_tf32(float& d0, float& d1, float& d2, float& d3,
                                         uint32_t a0, uint32_t a1, uint32_t a2, uint32_t a3,
                                         uint32_t b0, uint32_t b1) {
    asm volatile(
        "mma.sync.aligned.m16n8k8.row.col.f32.tf32.tf32.f32 "
        "{%0,%1,%2,%3},{%4,%5,%6,%7},{%8,%9},{%0,%1,%2,%3};"
        : "+f"(d0), "+f"(d1), "+f"(d2), "+f"(d3)
        : "r"(a0), "r"(a1), "r"(a2), "r"(a3), "r"(b0), "r"(b1));
}

__device__ __forceinline__ void mma_bf16(float& d0, float& d1, float& d2, float& d3,
                                         uint32_t a0, uint32_t a1, uint32_t a2, uint32_t a3,
                                         uint32_t b0, uint32_t b1) {
    asm volatile(
        "mma.sync.aligned.m16n8k16.row.col.f32.bf16.bf16.f32 "
        "{%0,%1,%2,%3},{%4,%5,%6,%7},{%8,%9},{%0,%1,%2,%3};"
        : "+f"(d0), "+f"(d1), "+f"(d2), "+f"(d3)
        : "r"(a0), "r"(a1), "r"(a2), "r"(a3), "r"(b0), "r"(b1));
}

// Split (x0, x1) -> hi pack {bf16(x1):bf16(x0)} and lo pack of the residuals.
__device__ __forceinline__ void bsplit2(float x0, float x1, uint32_t& hi, uint32_t& lo) {
    uint32_t h;
    asm("cvt.rn.bf16x2.f32 %0, %1, %2;" : "=r"(h) : "f"(x1), "f"(x0));
    float h1 = __uint_as_float(h & 0xFFFF0000u);
    float h0 = __uint_as_float(h << 16);
    float r0 = x0 - h0;
    float r1 = x1 - h1;
    asm("cvt.rn.bf16x2.f32 %0, %1, %2;" : "=r"(lo) : "f"(r1), "f"(r0));
    hi = h;
}

__device__ __forceinline__ void ldsm_x4(uint32_t& r0, uint32_t& r1, uint32_t& r2, uint32_t& r3,
                                        uint32_t addr) {
    asm volatile("ldmatrix.sync.aligned.m8n8.x4.shared.b16 {%0,%1,%2,%3}, [%4];"
        : "=r"(r0), "=r"(r1), "=r"(r2), "=r"(r3) : "r"(addr));
}
__device__ __forceinline__ void ldsm_x4_t(uint32_t& r0, uint32_t& r1, uint32_t& r2, uint32_t& r3,
                                          uint32_t addr) {
    asm volatile("ldmatrix.sync.aligned.m8n8.x4.trans.shared.b16 {%0,%1,%2,%3}, [%4];"
        : "=r"(r0), "=r"(r1), "=r"(r2), "=r"(r3) : "r"(addr));
}

// ---------------------------------------------------------------------------
// 3xBF16 tensor-core GEMM, R11: BM=128, BN=128, warp tile 64x32 (2m x 4n),
// 256 threads, 1 CTA/SM. bf16-resident smem + ldmatrix fragment loads.
// mode 0: N=3072, scatter into g_q/g_k/g_v with q-scale (QKV projection)
// mode 1: N=1024, A := g_attn, plain write to out (output projection)
// ---------------------------------------------------------------------------
__global__ __launch_bounds__(256) void gemm_tc_kernel(
    const float* __restrict__ A, const float* __restrict__ Bm,
    const float* __restrict__ bias, float* __restrict__ out,
    const int* __restrict__ lidx, int N, int mode)
{
    const int K = 1024;
    __shared__ __nv_bfloat16 AhiS[128][40];
    __shared__ __nv_bfloat16 AloS[128][40];
    __shared__ __nv_bfloat16 BhiS[32][136];
    __shared__ __nv_bfloat16 BloS[32][136];

    const float* Ap = (mode == 1) ? (const float*)g_attn : A;

    int tid = threadIdx.x;
    int bm = blockIdx.y;
    int bn = blockIdx.x;
    int lane = tid & 31, warp = tid >> 5;
    int wm = (warp >> 2) * 64;      // 2 m-warps (64 rows each)
    int wn = (warp & 3) * 32;       // 4 n-warps (32 cols each)
    int r = lane >> 2;
    int c = lane & 3;

    const float* Ab = Ap + (size_t)bm * 128 * K;
    const float* Bb = Bm + (size_t)bn * 128;

    // gmem load assignment
    int aM = tid >> 1;              // 0..127
    int aK = (tid & 1) * 16;        // 0 or 16
    int bK = tid >> 3;              // 0..31
    int bN = (tid & 7) * 4;         // 0..28 (j strides by 32 -> coalesced 128B)

    int lr   = lane & 7;
    int lm8  = (lane >> 3) & 1;
    int lhi  = (lane >> 4) & 1;
    uint32_t aHiB = (uint32_t)__cvta_generic_to_shared(&AhiS[0][0]);
    uint32_t aLoB = (uint32_t)__cvta_generic_to_shared(&AloS[0][0]);
    uint32_t bHiB = (uint32_t)__cvta_generic_to_shared(&BhiS[0][0]);
    uint32_t bLoB = (uint32_t)__cvta_generic_to_shared(&BloS[0][0]);
    int aRowL = wm + lr + lm8 * 8;
    int bRowL = lr + lm8 * 8;

    float acc[4][4][4];             // [mi m16-tile][ni n8-tile][e]
    #pragma unroll
    for (int mi = 0; mi < 4; mi++)
        #pragma unroll
        for (int ni = 0; ni < 4; ni++)
            #pragma unroll
            for (int e = 0; e < 4; e++) acc[mi][ni][e] = 0.f;

    float4 aPref[4];
    float4 bPref[4];
    #pragma unroll
    for (int j = 0; j < 4; j++) {
        aPref[j] = *(const float4*)(Ab + (size_t)aM * K + aK + j * 4);
        bPref[j] = *(const float4*)(Bb + (size_t)bK * N + bN + j * 32);
    }

    for (int k0 = 0; k0 < K; k0 += 32) {
        {
            uint32_t hp[8], lp[8];
            #pragma unroll
            for (int j = 0; j < 4; j++) {
                bsplit2(aPref[j].x, aPref[j].y, hp[2*j],   lp[2*j]);
                bsplit2(aPref[j].z, aPref[j].w, hp[2*j+1], lp[2*j+1]);
            }
            *(uint4*)&AhiS[aM][aK]     = make_uint4(hp[0], hp[1], hp[2], hp[3]);
            *(uint4*)&AhiS[aM][aK + 8] = make_uint4(hp[4], hp[5], hp[6], hp[7]);
            *(uint4*)&AloS[aM][aK]     = make_uint4(lp[0], lp[1], lp[2], lp[3]);
            *(uint4*)&AloS[aM][aK + 8] = make_uint4(lp[4], lp[5], lp[6], lp[7]);

            #pragma unroll
            for (int j = 0; j < 4; j++) {
                uint32_t h0, l0, h1, l1;
                bsplit2(bPref[j].x, bPref[j].y, h0, l0);
                bsplit2(bPref[j].z, bPref[j].w, h1, l1);
                *(uint2*)&BhiS[bK][bN + j * 32] = make_uint2(h0, h1);
                *(uint2*)&BloS[bK][bN + j * 32] = make_uint2(l0, l1);
            }
        }
        __syncthreads();

        if (k0 + 32 < K) {
            #pragma unroll
            for (int j = 0; j < 4; j++) {
                aPref[j] = *(const float4*)(Ab + (size_t)aM * K + k0 + 32 + aK + j * 4);
                bPref[j] = *(const float4*)(Bb + (size_t)(k0 + 32 + bK) * N + bN + j * 32);
            }
        }

        #pragma unroll
        for (int ks = 0; ks < 2; ks++) {
            uint32_t ahi[4][4], alo[4][4];
            #pragma unroll
            for (int mi = 0; mi < 4; mi++) {
                uint32_t off = (uint32_t)(aRowL + mi * 16) * 80u + ks * 32u + lhi * 16u;
                ldsm_x4(ahi[mi][0], ahi[mi][1], ahi[mi][2], ahi[mi][3], aHiB + off);
                ldsm_x4(alo[mi][0], alo[mi][1], alo[mi][2], alo[mi][3], aLoB + off);
            }
            uint32_t bhi[2][4], blo[2][4];
            #pragma unroll
            for (int p = 0; p < 2; p++) {
                uint32_t off = (uint32_t)(ks * 16 + bRowL) * 272u
                             + (uint32_t)(wn + p * 16 + lhi * 8) * 2u;
                ldsm_x4_t(bhi[p][0], bhi[p][1], bhi[p][2], bhi[p][3], bHiB + off);
                ldsm_x4_t(blo[p][0], blo[p][1], blo[p][2], blo[p][3], bLoB + off);
            }
            #pragma unroll
            for (int mi = 0; mi < 4; mi++)
                #pragma unroll
                for (int p = 0; p < 2; p++)
                    #pragma unroll
                    for (int q = 0; q < 2; q++) {
                        float* d = acc[mi][2 * p + q];
                        uint32_t b0h = bhi[p][2*q], b1h = bhi[p][2*q+1];
                        uint32_t b0l = blo[p][2*q], b1l = blo[p][2*q+1];
                        mma_bf16(d[0], d[1], d[2], d[3],
                                 ahi[mi][0], ahi[mi][1], ahi[mi][2], ahi[mi][3], b0h, b1h);
                        mma_bf16(d[0], d[1], d[2], d[3],
                                 ahi[mi][0], ahi[mi][1], ahi[mi][2], ahi[mi][3], b0l, b1l);
                        mma_bf16(d[0], d[1], d[2], d[3],
                                 alo[mi][0], alo[mi][1], alo[mi][2], alo[mi][3], b0h, b1h);
                    }
        }
        __syncthreads();
    }

    // Epilogue. acc elem e: row = r + (e>>1)*8, col = c*2 + (e&1)
    if (mode == 0) {
        float scale = 0.125f / (float)(lidx[0] + 1);
        #pragma unroll
        for (int mi = 0; mi < 4; mi++) {
            #pragma unroll
            for (int ni = 0; ni < 4; ni++) {
                #pragma unroll
                for (int e = 0; e < 4; e++) {
                    int m = bm * 128 + wm + mi * 16 + r + (e >> 1) * 8;
                    int n = bn * 128 + wn + ni * 8 + c * 2 + (e & 1);
                    float v = acc[mi][ni][e] + bias[n];
                    int b = m >> 11, s = m & 2047;
                    int t = n >> 10;
                    int hd = n & 1023;
                    int h = hd >> 6, d = hd & 63;
                    size_t idx = ((size_t)(b * HSZ + h) * SSZ + s) * DSZ + d;
                    if (t == 0)      g_q[idx] = v * scale;
                    else if (t == 1) g_k[idx] = v;
                    else             g_v[idx] = v;
                }
            }
        }
    } else {
        #pragma unroll
        for (int mi = 0; mi < 4; mi++) {
            #pragma unroll
            for (int ni = 0; ni < 4; ni++) {
                #pragma unroll
                for (int e = 0; e < 4; e++) {
                    int m = bm * 128 + wm + mi * 16 + r + (e >> 1) * 8;
                    int n = bn * 128 + wn + ni * 8 + c * 2 + (e & 1);
                    out[(size_t)m * N + n] = acc[mi][ni][e] + bias[n];
                }
            }
        }
    }
}

// ---------------------------------------------------------------------------
// Tensor-core flash attention (unchanged from R10).
// ---------------------------------------------------------------------------
__global__ __launch_bounds__(256, 1) void attn_tc_kernel()
{
    extern __shared__ char smc[];
    uint32_t* KsW = (uint32_t*)smc;                         // [64][68] tf32 bits
    char* VhiC = smc + 17408;                               // [64][72] bf16
    char* VloC = smc + 26624;
    char* PhiC = smc + 35840;                               // [128][72] bf16
    char* PloC = smc + 54272;

    uint32_t ksB  = (uint32_t)__cvta_generic_to_shared(KsW);
    uint32_t vhiB = (uint32_t)__cvta_generic_to_shared(VhiC);
    uint32_t vloB = (uint32_t)__cvta_generic_to_shared(VloC);
    uint32_t phiB = (uint32_t)__cvta_generic_to_shared(PhiC);
    uint32_t ploB = (uint32_t)__cvta_generic_to_shared(PloC);

    int bh = blockIdx.y;
    int qb = 15 - blockIdx.x;
    int q0 = qb * 128;

    const float* qp = g_q + (size_t)bh * SSZ * DSZ + (size_t)q0 * DSZ;
    const float* kb = g_k + (size_t)bh * SSZ * DSZ;
    const float* vb = g_v + (size_t)bh * SSZ * DSZ;

    int tid = threadIdx.x, lane = tid & 31, warp = tid >> 5;
    int r = lane >> 2, c = lane & 3;
    int wr0 = warp * 16;
    int lr  = lane & 7;
    int lm8 = (lane >> 3) & 1;
    int lhi = (lane >> 4) & 1;
    int g   = lane >> 3;
    int kdn = (g & 1) * 8;
    int kdk = (g >> 1) * 4;

    {
        float (*Qs)[QPAD] = (float(*)[QPAD])smc;
        for (int i = tid; i < 128 * 16; i += 256) {
            int row = i >> 4, col4 = (i & 15) * 4;
            *(float4*)&Qs[row][col4] = *(const float4*)(qp + row * 64 + col4);
        }
        __syncthreads();
    }
    uint32_t qa[8][4];
    {
        float (*Qs)[QPAD] = (float(*)[QPAD])smc;
        #pragma unroll
        for (int ks = 0; ks < 8; ks++) {
            int k8 = ks * 8;
            qa[ks][0] = f2tf32(Qs[wr0 + r][k8 + c]);
            qa[ks][1] = f2tf32(Qs[wr0 + r + 8][k8 + c]);
            qa[ks][2] = f2tf32(Qs[wr0 + r][k8 + c + 4]);
            qa[ks][3] = f2tf32(Qs[wr0 + r + 8][k8 + c + 4]);
        }
    }

    float m0 = -1e30f, m1 = -1e30f, l0 = 0.f, l1 = 0.f;
    float o[8][4];
    #pragma unroll
    for (int ni = 0; ni < 8; ni++)
        #pragma unroll
        for (int e = 0; e < 4; e++) o[ni][e] = 0.f;

    int qrow0 = q0 + wr0 + r;
    int qrow1 = qrow0 + 8;

    int ntiles = (qb + 1) * 2;
    for (int kt = 0; kt < ntiles; kt++) {
        __syncthreads();
        const float* kp = kb + (size_t)kt * 64 * DSZ;
        const float* vp = vb + (size_t)kt * 64 * DSZ;
        for (int i = tid; i < 1024; i += 256) {
            int row = i >> 4, col4 = (i & 15) * 4;
            float4 k4 = *(const float4*)(kp + row * 64 + col4);
            uint4 kt4;
            kt4.x = f2tf32(k4.x); kt4.y = f2tf32(k4.y);
            kt4.z = f2tf32(k4.z); kt4.w = f2tf32(k4.w);
            *(uint4*)&KsW[row * KPADF + col4] = kt4;

            float4 v4 = *(const float4*)(vp + row * 64 + col4);
            uint32_t h0, l0r, h1, l1r;
            bsplit2(v4.x, v4.y, h0, l0r);
            bsplit2(v4.z, v4.w, h1, l1r);
            *(uint2*)(VhiC + row * (VPADB*2) + col4 * 2) = make_uint2(h0, h1);
            *(uint2*)(VloC + row * (VPADB*2) + col4 * 2) = make_uint2(l0r, l1r);
        }
        __syncthreads();

        float s[8][4];
        #pragma unroll
        for (int ni = 0; ni < 8; ni++)
            #pragma unroll
            for (int e = 0; e < 4; e++) s[ni][e] = 0.f;

        #pragma unroll
        for (int ks = 0; ks < 8; ks++) {
            int k8 = ks * 8;
            #pragma unroll
            for (int np = 0; np < 4; np++) {
                uint32_t kb0, kb1, kb2, kb3;
                uint32_t off = (uint32_t)((np * 16 + kdn + lr) * KPADF + k8 + kdk) * 4u;
                ldsm_x4(kb0, kb1, kb2, kb3, ksB + off);
                mma_tf32(s[2*np][0], s[2*np][1], s[2*np][2], s[2*np][3],
                         qa[ks][0], qa[ks][1], qa[ks][2], qa[ks][3], kb0, kb2);
                mma_tf32(s[2*np+1][0], s[2*np+1][1], s[2*np+1][2], s[2*np+1][3],
                         qa[ks][0], qa[ks][1], qa[ks][2], qa[ks][3], kb1, kb3);
            }
        }

        if (kt * 64 + 63 > qrow0) {
            #pragma unroll
            for (int ni = 0; ni < 8; ni++) {
                int key = kt * 64 + ni * 8 + 2 * c;
                if (key     > qrow0) s[ni][0] = -1e30f;
                if (key + 1 > qrow0) s[ni][1] = -1e30f;
                if (key     > qrow1) s[ni][2] = -1e30f;
                if (key + 1 > qrow1) s[ni][3] = -1e30f;
            }
        }

        float mx0 = -1e30f, mx1 = -1e30f;
        #pragma unroll
        for (int ni = 0; ni < 8; ni++) {
            mx0 = fmaxf(mx0, fmaxf(s[ni][0], s[ni][1]));
            mx1 = fmaxf(mx1, fmaxf(s[ni][2], s[ni][3]));
        }
        mx0 = fmaxf(mx0, __shfl_xor_sync(0xffffffffu, mx0, 1));
        mx0 = fmaxf(mx0, __shfl_xor_sync(0xffffffffu, mx0, 2));
        mx1 = fmaxf(mx1, __shfl_xor_sync(0xffffffffu, mx1, 1));
        mx1 = fmaxf(mx1, __shfl_xor_sync(0xffffffffu, mx1, 2));

        float mn0 = fmaxf(m0, mx0), mn1 = fmaxf(m1, mx1);
        float sum0 = 0.f, sum1 = 0.f;
        #pragma unroll
        for (int ni = 0; ni < 8; ni++) {
            float p0 = __expf(s[ni][0] - mn0);
            float p1 = __expf(s[ni][1] - mn0);
            float p2 = __expf(s[ni][2] - mn1);
            float p3 = __expf(s[ni][3] - mn1);
            sum0 += p0 + p1;
            sum1 += p2 + p3;
            uint32_t h, lw;
            int byte0 = (wr0 + r) * (PPADB*2) + (ni * 8 + 2 * c) * 2;
            int byte1 = (wr0 + r + 8) * (PPADB*2) + (ni * 8 + 2 * c) * 2;
            bsplit2(p0, p1, h, lw);
            *(uint32_t*)(PhiC + byte0) = h;
            *(uint32_t*)(PloC + byte0) = lw;
            bsplit2(p2, p3, h, lw);
            *(uint32_t*)(PhiC + byte1) = h;
            *(uint32_t*)(PloC + byte1) = lw;
        }
        sum0 += __shfl_xor_sync(0xffffffffu, sum0, 1);
        sum0 += __shfl_xor_sync(0xffffffffu, sum0, 2);
        sum1 += __shfl_xor_sync(0xffffffffu, sum1, 1);
        sum1 += __shfl_xor_sync(0xffffffffu, sum1, 2);

        float alpha0 = __expf(m0 - mn0);
        float alpha1 = __expf(m1 - mn1);
        l0 = l0 * alpha0 + sum0;  m0 = mn0;
        l1 = l1 * alpha1 + sum1;  m1 = mn1;
        #pragma unroll
        for (int ni = 0; ni < 8; ni++) {
            o[ni][0] *= alpha0; o[ni][1] *= alpha0;
            o[ni][2] *= alpha1; o[ni][3] *= alpha1;
        }
        __syncwarp();

        #pragma unroll
        for (int ks = 0; ks < 4; ks++) {
            uint32_t phf[4], plf[4];
            uint32_t offP = (uint32_t)(wr0 + lr + lm8 * 8) * (PPADB*2)
                          + (uint32_t)(ks * 16 + lhi * 8) * 2u;
            ldsm_x4(phf[0], phf[1], phf[2], phf[3], phiB + offP);
            ldsm_x4(plf[0], plf[1], plf[2], plf[3], ploB + offP);

            uint32_t vhf[4][4], vlf[4][4];
            #pragma unroll
            for (int p = 0; p < 4; p++) {
                uint32_t offV = (uint32_t)(ks * 16 + lr + lm8 * 8) * (VPADB*2)
                              + (uint32_t)(p * 16 + lhi * 8) * 2u;
                ldsm_x4_t(vhf[p][0], vhf[p][1], vhf[p][2], vhf[p][3], vhiB + offV);
                ldsm_x4_t(vlf[p][0], vlf[p][1], vlf[p][2], vlf[p][3], vloB + offV);
            }
            #pragma unroll
            for (int p = 0; p < 4; p++)
                #pragma unroll
                for (int q = 0; q < 2; q++) {
                    float* d = o[2 * p + q];
                    uint32_t b0h = vhf[p][2*q], b1h = vhf[p][2*q+1];
                    uint32_t b0l = vlf[p][2*q], b1l = vlf[p][2*q+1];
                    mma_bf16(d[0], d[1], d[2], d[3],
                             phf[0], phf[1], phf[2], phf[3], b0h, b1h);
                    mma_bf16(d[0], d[1], d[2], d[3],
                             phf[0], phf[1], phf[2], phf[3], b0l, b1l);
                    mma_bf16(d[0], d[1], d[2], d[3],
                             plf[0], plf[1], plf[2], plf[3], b0h, b1h);
                }
        }
    }

    int b = bh >> 4, h = bh & 15;
    float inv0 = 1.f / l0, inv1 = 1.f / l1;
    int s0 = q0 + wr0 + r, s1 = s0 + 8;
    size_t base0 = ((size_t)(b * SSZ + s0) * HSZ + h) * DSZ;
    size_t base1 = ((size_t)(b * SSZ + s1) * HSZ + h) * DSZ;
    #pragma unroll
    for (int ni = 0; ni < 8; ni++) {
        int d0 = ni * 8 + 2 * c;
        *(float2*)&g_attn[base0 + d0] = make_float2(o[ni][0] * inv0, o[ni][1] * inv0);
        *(float2*)&g_attn[base1 + d0] = make_float2(o[ni][2] * inv1, o[ni][3] * inv1);
    }
}

extern "C" void kernel_launch(void* const* d_in, const int* in_sizes, int n_in,
                              void* d_out, int out_size)
{
    const float* hidden = (const float*)d_in[0];
    const float* Wqkv  = (const float*)d_in[2];
    const float* bqkv  = (const float*)d_in[3];
    const float* Wproj = (const float*)d_in[4];
    const float* bproj = (const float*)d_in[5];
    const int*   lidx  = (const int*)d_in[6];
    float* out = (float*)d_out;

    const int attn_smem = 72704;
    cudaFuncSetAttribute(attn_tc_kernel,
        cudaFuncAttributeMaxDynamicSharedMemorySize, attn_smem);

    // QKV projection: M=8192, N=3072, K=1024  (BN=128 -> 24 n-blocks)
    gemm_tc_kernel<<<dim3(24, 64), 256>>>(hidden, Wqkv, bqkv, nullptr, lidx, 3072, 0);
    // Attention: 16 query tiles (128 rows each) x 64 (b,h) pairs
    attn_tc_kernel<<<dim3(16, 64), 256, attn_smem>>>();
    // Output projection: M=8192, N=1024, K=1024  (BN=128 -> 8 n-blocks)
    gemm_tc_kernel<<<dim3(8, 64), 256>>>(nullptr, Wproj, bproj, out, lidx, 1024, 1);
}

// round 12
// speedup vs baseline: 1.9277x; 1.0800x over previous
#include <cuda_runtime.h>
#include <cuda_bf16.h>
#include <math.h>
#include <stdint.h>

#define BSZ 4
#define SSZ 2048
#define ESZ 1024
#define HSZ 16
#define DSZ 64

#define QPAD 68    // attn: Q staging stride (fp32)
#define KPADF 68   // attn: K smem stride (fp32/tf32 words)
#define PPADB 72   // attn: P smem stride (bf16)
#define VPADB 72   // attn: V smem stride (bf16)

// GEMM double-buffer smem layout (bytes within one stage)
#define G_STG   37888   // stage stride
#define G_ALO   10240
#define G_BHI   20480
#define G_BLO   29184
#define G_TOTAL 75776

// Scratch (allocation-free): Q/K/V laid out [B][H][S][D]; attn out [B][S][H][D]
__device__ float g_q[BSZ*HSZ*SSZ*DSZ];
__device__ float g_k[BSZ*HSZ*SSZ*DSZ];
__device__ float g_v[BSZ*HSZ*SSZ*DSZ];
__device__ float g_attn[BSZ*SSZ*HSZ*DSZ];

__device__ __forceinline__ uint32_t f2tf32(float x) {
    uint32_t r;
    asm("cvt.rna.tf32.f32 %0, %1;" : "=r"(r) : "f"(x));
    return r;
}

__device__ __forceinline__ void mma_tf32(float& d0, float& d1, float& d2, float& d3,
                                         uint32_t a0, uint32_t a1, uint32_t a2, uint32_t a3,
                                         uint32_t b0, uint32_t b1) {
    asm volatile(
        "mma.sync.aligned.m16n8k8.row.col.f32.tf32.tf32.f32 "
        "{%0,%1,%2,%3},{%4,%5,%6,%7},{%8,%9},{%0,%1,%2,%3};"
        : "+f"(d0), "+f"(d1), "+f"(d2), "+f"(d3)
        : "r"(a0), "r"(a1), "r"(a2), "r"(a3), "r"(b0), "r"(b1));
}

__device__ __forceinline__ void mma_bf16(float& d0, float& d1, float& d2, float& d3,
                                         uint32_t a0, uint32_t a1, uint32_t a2, uint32_t a3,
                                         uint32_t b0, uint32_t b1) {
    asm volatile(
        "mma.sync.aligned.m16n8k16.row.col.f32.bf16.bf16.f32 "
        "{%0,%1,%2,%3},{%4,%5,%6,%7},{%8,%9},{%0,%1,%2,%3};"
        : "+f"(d0), "+f"(d1), "+f"(d2), "+f"(d3)
        : "r"(a0), "r"(a1), "r"(a2), "r"(a3), "r"(b0), "r"(b1));
}

// Split (x0, x1) -> hi pack {bf16(x1):bf16(x0)} and lo pack of the residuals.
__device__ __forceinline__ void bsplit2(float x0, float x1, uint32_t& hi, uint32_t& lo) {
    uint32_t h;
    asm("cvt.rn.bf16x2.f32 %0, %1, %2;" : "=r"(h) : "f"(x1), "f"(x0));
    float h1 = __uint_as_float(h & 0xFFFF0000u);
    float h0 = __uint_as_float(h << 16);
    float r0 = x0 - h0;
    float r1 = x1 - h1;
    asm("cvt.rn.bf16x2.f32 %0, %1, %2;" : "=r"(lo) : "f"(r1), "f"(r0));
    hi = h;
}

__device__ __forceinline__ void ldsm_x4(uint32_t& r0, uint32_t& r1, uint32_t& r2, uint32_t& r3,
                                        uint32_t addr) {
    asm volatile("ldmatrix.sync.aligned.m8n8.x4.shared.b16 {%0,%1,%2,%3}, [%4];"
        : "=r"(r0), "=r"(r1), "=r"(r2), "=r"(r3) : "r"(addr));
}
__device__ __forceinline__ void ldsm_x4_t(uint32_t& r0, uint32_t& r1, uint32_t& r2, uint32_t& r3,
                                          uint32_t addr) {
    asm volatile("ldmatrix.sync.aligned.m8n8.x4.trans.shared.b16 {%0,%1,%2,%3}, [%4];"
        : "=r"(r0), "=r"(r1), "=r"(r2), "=r"(r3) : "r"(addr));
}

// ---------------------------------------------------------------------------
// 3xBF16 tensor-core GEMM, R12: 2-stage smem ping-pong, ONE sync per chunk,
// compute-first ordering. BM=128, BN=128, warp tile 64x32 (2m x 4n).
// mode 0: N=3072, scatter into g_q/g_k/g_v with q-scale (QKV projection)
// mode 1: N=1024, A := g_attn, plain write to out (output projection)
// ---------------------------------------------------------------------------
__global__ __launch_bounds__(256) void gemm_tc_kernel(
    const float* __restrict__ A, const float* __restrict__ Bm,
    const float* __restrict__ bias, float* __restrict__ out,
    const int* __restrict__ lidx, int N, int mode)
{
    const int K = 1024;
    extern __shared__ char smg[];
    uint32_t smB = (uint32_t)__cvta_generic_to_shared(smg);

    const float* Ap = (mode == 1) ? (const float*)g_attn : A;

    int tid = threadIdx.x;
    int bm = blockIdx.y;
    int bn = blockIdx.x;
    int lane = tid & 31, warp = tid >> 5;
    int wm = (warp >> 2) * 64;      // 2 m-warps (64 rows each)
    int wn = (warp & 3) * 32;       // 4 n-warps (32 cols each)
    int r = lane >> 2;
    int c = lane & 3;

    const float* Ab = Ap + (size_t)bm * 128 * K;
    const float* Bb = Bm + (size_t)bn * 128;

    // gmem load assignment
    int aM = tid >> 1;              // 0..127
    int aK = (tid & 1) * 16;        // 0 or 16
    int bK = tid >> 3;              // 0..31
    int bN = (tid & 7) * 4;         // 0..28 (j strides by 32 -> coalesced)

    int lr   = lane & 7;
    int lm8  = (lane >> 3) & 1;
    int lhi  = (lane >> 4) & 1;
    int aRowL = wm + lr + lm8 * 8;
    int bRowL = lr + lm8 * 8;

    // per-thread store byte offsets (within a stage)
    uint32_t aStO = (uint32_t)aM * 80u + (uint32_t)aK * 2u;    // Ahi region
    uint32_t bStO = (uint32_t)bK * 272u + (uint32_t)bN * 2u;   // Bhi region

    float acc[4][4][4];
    #pragma unroll
    for (int mi = 0; mi < 4; mi++)
        #pragma unroll
        for (int ni = 0; ni < 4; ni++)
            #pragma unroll
            for (int e = 0; e < 4; e++) acc[mi][ni][e] = 0.f;

    float4 aPref[4];
    float4 bPref[4];
    #pragma unroll
    for (int j = 0; j < 4; j++) {
        aPref[j] = *(const float4*)(Ab + (size_t)aM * K + aK + j * 4);
        bPref[j] = *(const float4*)(Bb + (size_t)bK * N + bN + j * 32);
    }

    // commit chunk in regs to stage s
    auto commit = [&](int s) {
        char* st = smg + s * G_STG;
        uint32_t hp[8], lp[8];
        #pragma unroll
        for (int j = 0; j < 4; j++) {
            bsplit2(aPref[j].x, aPref[j].y, hp[2*j],   lp[2*j]);
            bsplit2(aPref[j].z, aPref[j].w, hp[2*j+1], lp[2*j+1]);
        }
        *(uint4*)(st + aStO)              = make_uint4(hp[0], hp[1], hp[2], hp[3]);
        *(uint4*)(st + aStO + 16)         = make_uint4(hp[4], hp[5], hp[6], hp[7]);
        *(uint4*)(st + G_ALO + aStO)      = make_uint4(lp[0], lp[1], lp[2], lp[3]);
        *(uint4*)(st + G_ALO + aStO + 16) = make_uint4(lp[4], lp[5], lp[6], lp[7]);
        #pragma unroll
        for (int j = 0; j < 4; j++) {
            uint32_t h0, l0, h1, l1;
            bsplit2(bPref[j].x, bPref[j].y, h0, l0);
            bsplit2(bPref[j].z, bPref[j].w, h1, l1);
            *(uint2*)(st + G_BHI + bStO + j * 64) = make_uint2(h0, h1);
            *(uint2*)(st + G_BLO + bStO + j * 64) = make_uint2(l0, l1);
        }
    };

    commit(0);
    __syncthreads();

    const int NCHUNK = K / 32;      // 32
    for (int cI = 0; cI < NCHUNK; cI++) {
        // LDG next chunk (latency hidden under compute below)
        if (cI + 1 < NCHUNK) {
            int k0 = (cI + 1) * 32;
            #pragma unroll
            for (int j = 0; j < 4; j++) {
                aPref[j] = *(const float4*)(Ab + (size_t)aM * K + k0 + aK + j * 4);
                bPref[j] = *(const float4*)(Bb + (size_t)(k0 + bK) * N + bN + j * 32);
            }
        }

        // COMPUTE current stage
        uint32_t stO = (uint32_t)(cI & 1) * G_STG;
        #pragma unroll
        for (int ks = 0; ks < 2; ks++) {
            uint32_t ahi[4][4], alo[4][4];
            #pragma unroll
            for (int mi = 0; mi < 4; mi++) {
                uint32_t off = stO + (uint32_t)(aRowL + mi * 16) * 80u + ks * 32u + lhi * 16u;
                ldsm_x4(ahi[mi][0], ahi[mi][1], ahi[mi][2], ahi[mi][3], smB + off);
                ldsm_x4(alo[mi][0], alo[mi][1], alo[mi][2], alo[mi][3], smB + G_ALO + off);
            }
            uint32_t bhi[2][4], blo[2][4];
            #pragma unroll
            for (int p = 0; p < 2; p++) {
                uint32_t off = stO + (uint32_t)(ks * 16 + bRowL) * 272u
                             + (uint32_t)(wn + p * 16 + lhi * 8) * 2u;
                ldsm_x4_t(bhi[p][0], bhi[p][1], bhi[p][2], bhi[p][3], smB + G_BHI + off);
                ldsm_x4_t(blo[p][0], blo[p][1], blo[p][2], blo[p][3], smB + G_BLO + off);
            }
            #pragma unroll
            for (int mi = 0; mi < 4; mi++)
                #pragma unroll
                for (int p = 0; p < 2; p++)
                    #pragma unroll
                    for (int q = 0; q < 2; q++) {
                        float* d = acc[mi][2 * p + q];
                        uint32_t b0h = bhi[p][2*q], b1h = bhi[p][2*q+1];
                        uint32_t b0l = blo[p][2*q], b1l = blo[p][2*q+1];
                        mma_bf16(d[0], d[1], d[2], d[3],
                                 ahi[mi][0], ahi[mi][1], ahi[mi][2], ahi[mi][3], b0h, b1h);
                        mma_bf16(d[0], d[1], d[2], d[3],
                                 ahi[mi][0], ahi[mi][1], ahi[mi][2], ahi[mi][3], b0l, b1l);
                        mma_bf16(d[0], d[1], d[2], d[3],
                                 alo[mi][0], alo[mi][1], alo[mi][2], alo[mi][3], b0h, b1h);
                    }
        }

        // commit next chunk into the other stage (overlaps other warps' compute)
        if (cI + 1 < NCHUNK)
            commit((cI + 1) & 1);
        __syncthreads();
    }

    // Epilogue. acc elem e: row = r + (e>>1)*8, col = c*2 + (e&1)
    if (mode == 0) {
        float scale = 0.125f / (float)(lidx[0] + 1);
        #pragma unroll
        for (int mi = 0; mi < 4; mi++) {
            #pragma unroll
            for (int ni = 0; ni < 4; ni++) {
                #pragma unroll
                for (int e = 0; e < 4; e++) {
                    int m = bm * 128 + wm + mi * 16 + r + (e >> 1) * 8;
                    int n = bn * 128 + wn + ni * 8 + c * 2 + (e & 1);
                    float v = acc[mi][ni][e] + bias[n];
                    int b = m >> 11, s = m & 2047;
                    int t = n >> 10;
                    int hd = n & 1023;
                    int h = hd >> 6, d = hd & 63;
                    size_t idx = ((size_t)(b * HSZ + h) * SSZ + s) * DSZ + d;
                    if (t == 0)      g_q[idx] = v * scale;
                    else if (t == 1) g_k[idx] = v;
                    else             g_v[idx] = v;
                }
            }
        }
    } else {
        #pragma unroll
        for (int mi = 0; mi < 4; mi++) {
            #pragma unroll
            for (int ni = 0; ni < 4; ni++) {
                #pragma unroll
                for (int e = 0; e < 4; e++) {
                    int m = bm * 128 + wm + mi * 16 + r + (e >> 1) * 8;
                    int n = bn * 128 + wn + ni * 8 + c * 2 + (e & 1);
                    out[(size_t)m * N + n] = acc[mi][ni][e] + bias[n];
                }
            }
        }
    }
}

// ---------------------------------------------------------------------------
// Tensor-core flash attention (unchanged from R10/R11).
// ---------------------------------------------------------------------------
__global__ __launch_bounds__(256, 1) void attn_tc_kernel()
{
    extern __shared__ char smc[];
    uint32_t* KsW = (uint32_t*)smc;                         // [64][68] tf32 bits
    char* VhiC = smc + 17408;                               // [64][72] bf16
    char* VloC = smc + 26624;
    char* PhiC = smc + 35840;                               // [128][72] bf16
    char* PloC = smc + 54272;

    uint32_t ksB  = (uint32_t)__cvta_generic_to_shared(KsW);
    uint32_t vhiB = (uint32_t)__cvta_generic_to_shared(VhiC);
    uint32_t vloB = (uint32_t)__cvta_generic_to_shared(VloC);
    uint32_t phiB = (uint32_t)__cvta_generic_to_shared(PhiC);
    uint32_t ploB = (uint32_t)__cvta_generic_to_shared(PloC);

    int bh = blockIdx.y;
    int qb = 15 - blockIdx.x;
    int q0 = qb * 128;

    const float* qp = g_q + (size_t)bh * SSZ * DSZ + (size_t)q0 * DSZ;
    const float* kb = g_k + (size_t)bh * SSZ * DSZ;
    const float* vb = g_v + (size_t)bh * SSZ * DSZ;

    int tid = threadIdx.x, lane = tid & 31, warp = tid >> 5;
    int r = lane >> 2, c = lane & 3;
    int wr0 = warp * 16;
    int lr  = lane & 7;
    int lm8 = (lane >> 3) & 1;
    int lhi = (lane >> 4) & 1;
    int g   = lane >> 3;
    int kdn = (g & 1) * 8;
    int kdk = (g >> 1) * 4;

    {
        float (*Qs)[QPAD] = (float(*)[QPAD])smc;
        for (int i = tid; i < 128 * 16; i += 256) {
            int row = i >> 4, col4 = (i & 15) * 4;
            *(float4*)&Qs[row][col4] = *(const float4*)(qp + row * 64 + col4);
        }
        __syncthreads();
    }
    uint32_t qa[8][4];
    {
        float (*Qs)[QPAD] = (float(*)[QPAD])smc;
        #pragma unroll
        for (int ks = 0; ks < 8; ks++) {
            int k8 = ks * 8;
            qa[ks][0] = f2tf32(Qs[wr0 + r][k8 + c]);
            qa[ks][1] = f2tf32(Qs[wr0 + r + 8][k8 + c]);
            qa[ks][2] = f2tf32(Qs[wr0 + r][k8 + c + 4]);
            qa[ks][3] = f2tf32(Qs[wr0 + r + 8][k8 + c + 4]);
        }
    }

    float m0 = -1e30f, m1 = -1e30f, l0 = 0.f, l1 = 0.f;
    float o[8][4];
    #pragma unroll
    for (int ni = 0; ni < 8; ni++)
        #pragma unroll
        for (int e = 0; e < 4; e++) o[ni][e] = 0.f;

    int qrow0 = q0 + wr0 + r;
    int qrow1 = qrow0 + 8;

    int ntiles = (qb + 1) * 2;
    for (int kt = 0; kt < ntiles; kt++) {
        __syncthreads();
        const float* kp = kb + (size_t)kt * 64 * DSZ;
        const float* vp = vb + (size_t)kt * 64 * DSZ;
        for (int i = tid; i < 1024; i += 256) {
            int row = i >> 4, col4 = (i & 15) * 4;
            float4 k4 = *(const float4*)(kp + row * 64 + col4);
            uint4 kt4;
            kt4.x = f2tf32(k4.x); kt4.y = f2tf32(k4.y);
            kt4.z = f2tf32(k4.z); kt4.w = f2tf32(k4.w);
            *(uint4*)&KsW[row * KPADF + col4] = kt4;

            float4 v4 = *(const float4*)(vp + row * 64 + col4);
            uint32_t h0, l0r, h1, l1r;
            bsplit2(v4.x, v4.y, h0, l0r);
            bsplit2(v4.z, v4.w, h1, l1r);
            *(uint2*)(VhiC + row * (VPADB*2) + col4 * 2) = make_uint2(h0, h1);
            *(uint2*)(VloC + row * (VPADB*2) + col4 * 2) = make_uint2(l0r, l1r);
        }
        __syncthreads();

        float s[8][4];
        #pragma unroll
        for (int ni = 0; ni < 8; ni++)
            #pragma unroll
            for (int e = 0; e < 4; e++) s[ni][e] = 0.f;

        #pragma unroll
        for (int ks = 0; ks < 8; ks++) {
            int k8 = ks * 8;
            #pragma unroll
            for (int np = 0; np < 4; np++) {
                uint32_t kb0, kb1, kb2, kb3;
                uint32_t off = (uint32_t)((np * 16 + kdn + lr) * KPADF + k8 + kdk) * 4u;
                ldsm_x4(kb0, kb1, kb2, kb3, ksB + off);
                mma_tf32(s[2*np][0], s[2*np][1], s[2*np][2], s[2*np][3],
                         qa[ks][0], qa[ks][1], qa[ks][2], qa[ks][3], kb0, kb2);
                mma_tf32(s[2*np+1][0], s[2*np+1][1], s[2*np+1][2], s[2*np+1][3],
                         qa[ks][0], qa[ks][1], qa[ks][2], qa[ks][3], kb1, kb3);
            }
        }

        if (kt * 64 + 63 > qrow0) {
            #pragma unroll
            for (int ni = 0; ni < 8; ni++) {
                int key = kt * 64 + ni * 8 + 2 * c;
                if (key     > qrow0) s[ni][0] = -1e30f;
                if (key + 1 > qrow0) s[ni][1] = -1e30f;
                if (key     > qrow1) s[ni][2] = -1e30f;
                if (key + 1 > qrow1) s[ni][3] = -1e30f;
            }
        }

        float mx0 = -1e30f, mx1 = -1e30f;
        #pragma unroll
        for (int ni = 0; ni < 8; ni++) {
            mx0 = fmaxf(mx0, fmaxf(s[ni][0], s[ni][1]));
            mx1 = fmaxf(mx1, fmaxf(s[ni][2], s[ni][3]));
        }
        mx0 = fmaxf(mx0, __shfl_xor_sync(0xffffffffu, mx0, 1));
        mx0 = fmaxf(mx0, __shfl_xor_sync(0xffffffffu, mx0, 2));
        mx1 = fmaxf(mx1, __shfl_xor_sync(0xffffffffu, mx1, 1));
        mx1 = fmaxf(mx1, __shfl_xor_sync(0xffffffffu, mx1, 2));

        float mn0 = fmaxf(m0, mx0), mn1 = fmaxf(m1, mx1);
        float sum0 = 0.f, sum1 = 0.f;
        #pragma unroll
        for (int ni = 0; ni < 8; ni++) {
            float p0 = __expf(s[ni][0] - mn0);
            float p1 = __expf(s[ni][1] - mn0);
            float p2 = __expf(s[ni][2] - mn1);
            float p3 = __expf(s[ni][3] - mn1);
            sum0 += p0 + p1;
            sum1 += p2 + p3;
            uint32_t h, lw;
            int byte0 = (wr0 + r) * (PPADB*2) + (ni * 8 + 2 * c) * 2;
            int byte1 = (wr0 + r + 8) * (PPADB*2) + (ni * 8 + 2 * c) * 2;
            bsplit2(p0, p1, h, lw);
            *(uint32_t*)(PhiC + byte0) = h;
            *(uint32_t*)(PloC + byte0) = lw;
            bsplit2(p2, p3, h, lw);
            *(uint32_t*)(PhiC + byte1) = h;
            *(uint32_t*)(PloC + byte1) = lw;
        }
        sum0 += __shfl_xor_sync(0xffffffffu, sum0, 1);
        sum0 += __shfl_xor_sync(0xffffffffu, sum0, 2);
        sum1 += __shfl_xor_sync(0xffffffffu, sum1, 1);
        sum1 += __shfl_xor_sync(0xffffffffu, sum1, 2);

        float alpha0 = __expf(m0 - mn0);
        float alpha1 = __expf(m1 - mn1);
        l0 = l0 * alpha0 + sum0;  m0 = mn0;
        l1 = l1 * alpha1 + sum1;  m1 = mn1;
        #pragma unroll
        for (int ni = 0; ni < 8; ni++) {
            o[ni][0] *= alpha0; o[ni][1] *= alpha0;
            o[ni][2] *= alpha1; o[ni][3] *= alpha1;
        }
        __syncwarp();

        #pragma unroll
        for (int ks = 0; ks < 4; ks++) {
            uint32_t phf[4], plf[4];
            uint32_t offP = (uint32_t)(wr0 + lr + lm8 * 8) * (PPADB*2)
                          + (uint32_t)(ks * 16 + lhi * 8) * 2u;
            ldsm_x4(phf[0], phf[1], phf[2], phf[3], phiB + offP);
            ldsm_x4(plf[0], plf[1], plf[2], plf[3], ploB + offP);

            uint32_t vhf[4][4], vlf[4][4];
            #pragma unroll
            for (int p = 0; p < 4; p++) {
                uint32_t offV = (uint32_t)(ks * 16 + lr + lm8 * 8) * (VPADB*2)
                              + (uint32_t)(p * 16 + lhi * 8) * 2u;
                ldsm_x4_t(vhf[p][0], vhf[p][1], vhf[p][2], vhf[p][3], vhiB + offV);
                ldsm_x4_t(vlf[p][0], vlf[p][1], vlf[p][2], vlf[p][3], vloB + offV);
            }
            #pragma unroll
            for (int p = 0; p < 4; p++)
                #pragma unroll
                for (int q = 0; q < 2; q++) {
                    float* d = o[2 * p + q];
                    uint32_t b0h = vhf[p][2*q], b1h = vhf[p][2*q+1];
                    uint32_t b0l = vlf[p][2*q], b1l = vlf[p][2*q+1];
                    mma_bf16(d[0], d[1], d[2], d[3],
                             phf[0], phf[1], phf[2], phf[3], b0h, b1h);
                    mma_bf16(d[0], d[1], d[2], d[3],
                             phf[0], phf[1], phf[2], phf[3], b0l, b1l);
                    mma_bf16(d[0], d[1], d[2], d[3],
                             plf[0], plf[1], plf[2], plf[3], b0h, b1h);
                }
        }
    }

    int b = bh >> 4, h = bh & 15;
    float inv0 = 1.f / l0, inv1 = 1.f / l1;
    int s0 = q0 + wr0 + r, s1 = s0 + 8;
    size_t base0 = ((size_t)(b * SSZ + s0) * HSZ + h) * DSZ;
    size_t base1 = ((size_t)(b * SSZ + s1) * HSZ + h) * DSZ;
    #pragma unroll
    for (int ni = 0; ni < 8; ni++) {
        int d0 = ni * 8 + 2 * c;
        *(float2*)&g_attn[base0 + d0] = make_float2(o[ni][0] * inv0, o[ni][1] * inv0);
        *(float2*)&g_attn[base1 + d0] = make_float2(o[ni][2] * inv1, o[ni][3] * inv1);
    }
}

extern "C" void kernel_launch(void* const* d_in, const int* in_sizes, int n_in,
                              void* d_out, int out_size)
{
    const float* hidden = (const float*)d_in[0];
    const float* Wqkv  = (const float*)d_in[2];
    const float* bqkv  = (const float*)d_in[3];
    const float* Wproj = (const float*)d_in[4];
    const float* bproj = (const float*)d_in[5];
    const int*   lidx  = (const int*)d_in[6];
    float* out = (float*)d_out;

    cudaFuncSetAttribute(gemm_tc_kernel,
        cudaFuncAttributeMaxDynamicSharedMemorySize, G_TOTAL);
    const int attn_smem = 72704;
    cudaFuncSetAttribute(attn_tc_kernel,
        cudaFuncAttributeMaxDynamicSharedMemorySize, attn_smem);

    // QKV projection: M=8192, N=3072, K=1024  (BN=128 -> 24 n-blocks)
    gemm_tc_kernel<<<dim3(24, 64), 256, G_TOTAL>>>(hidden, Wqkv, bqkv, nullptr, lidx, 3072, 0);
    // Attention: 16 query tiles (128 rows each) x 64 (b,h) pairs
    attn_tc_kernel<<<dim3(16, 64), 256, attn_smem>>>();
    // Output projection: M=8192, N=1024, K=1024  (BN=128 -> 8 n-blocks)
    gemm_tc_kernel<<<dim3(8, 64), 256, G_TOTAL>>>(nullptr, Wproj, bproj, out, lidx, 1024, 1);
}

// round 13
// speedup vs baseline: 2.3472x; 1.2176x over previous
#include <cuda_runtime.h>
#include <cuda_bf16.h>
#include <math.h>
#include <stdint.h>

#define BSZ 4
#define SSZ 2048
#define ESZ 1024
#define HSZ 16
#define DSZ 64

#define QPAD 68    // attn: Q staging stride (fp32)
#define KPADF 68   // attn: K smem stride (tf32 words)
#define PPADB 72   // attn: P smem stride (bf16)
#define VPADB 72   // attn: V smem stride (bf16)

// Attention double-buffer smem layout (bytes)
#define A_STG   35840   // stage stride: K 17408 + Vhi 9216 + Vlo 9216
#define A_VHI   17408
#define A_VLO   26624
#define A_PHI   71680
#define A_PLO   90112
#define A_TOTAL 108544

// GEMM double-buffer smem layout (bytes within one stage)
#define G_STG   37888
#define G_ALO   10240
#define G_BHI   20480
#define G_BLO   29184
#define G_TOTAL 75776

// Scratch (allocation-free): Q/K/V laid out [B][H][S][D]; attn out [B][S][H][D]
__device__ float g_q[BSZ*HSZ*SSZ*DSZ];
__device__ float g_k[BSZ*HSZ*SSZ*DSZ];
__device__ float g_v[BSZ*HSZ*SSZ*DSZ];
__device__ float g_attn[BSZ*SSZ*HSZ*DSZ];

__device__ __forceinline__ uint32_t f2tf32(float x) {
    uint32_t r;
    asm("cvt.rna.tf32.f32 %0, %1;" : "=r"(r) : "f"(x));
    return r;
}

__device__ __forceinline__ void mma_tf32(float& d0, float& d1, float& d2, float& d3,
                                         uint32_t a0, uint32_t a1, uint32_t a2, uint32_t a3,
                                         uint32_t b0, uint32_t b1) {
    asm volatile(
        "mma.sync.aligned.m16n8k8.row.col.f32.tf32.tf32.f32 "
        "{%0,%1,%2,%3},{%4,%5,%6,%7},{%8,%9},{%0,%1,%2,%3};"
        : "+f"(d0), "+f"(d1), "+f"(d2), "+f"(d3)
        : "r"(a0), "r"(a1), "r"(a2), "r"(a3), "r"(b0), "r"(b1));
}

__device__ __forceinline__ void mma_bf16(float& d0, float& d1, float& d2, float& d3,
                                         uint32_t a0, uint32_t a1, uint32_t a2, uint32_t a3,
                                         uint32_t b0, uint32_t b1) {
    asm volatile(
        "mma.sync.aligned.m16n8k16.row.col.f32.bf16.bf16.f32 "
        "{%0,%1,%2,%3},{%4,%5,%6,%7},{%8,%9},{%0,%1,%2,%3};"
        : "+f"(d0), "+f"(d1), "+f"(d2), "+f"(d3)
        : "r"(a0), "r"(a1), "r"(a2), "r"(a3), "r"(b0), "r"(b1));
}

// Split (x0, x1) -> hi pack {bf16(x1):bf16(x0)} and lo pack of the residuals.
__device__ __forceinline__ void bsplit2(float x0, float x1, uint32_t& hi, uint32_t& lo) {
    uint32_t h;
    asm("cvt.rn.bf16x2.f32 %0, %1, %2;" : "=r"(h) : "f"(x1), "f"(x0));
    float h1 = __uint_as_float(h & 0xFFFF0000u);
    float h0 = __uint_as_float(h << 16);
    float r0 = x0 - h0;
    float r1 = x1 - h1;
    asm("cvt.rn.bf16x2.f32 %0, %1, %2;" : "=r"(lo) : "f"(r1), "f"(r0));
    hi = h;
}

__device__ __forceinline__ void ldsm_x4(uint32_t& r0, uint32_t& r1, uint32_t& r2, uint32_t& r3,
                                        uint32_t addr) {
    asm volatile("ldmatrix.sync.aligned.m8n8.x4.shared.b16 {%0,%1,%2,%3}, [%4];"
        : "=r"(r0), "=r"(r1), "=r"(r2), "=r"(r3) : "r"(addr));
}
__device__ __forceinline__ void ldsm_x4_t(uint32_t& r0, uint32_t& r1, uint32_t& r2, uint32_t& r3,
                                          uint32_t addr) {
    asm volatile("ldmatrix.sync.aligned.m8n8.x4.trans.shared.b16 {%0,%1,%2,%3}, [%4];"
        : "=r"(r0), "=r"(r1), "=r"(r2), "=r"(r3) : "r"(addr));
}

// ---------------------------------------------------------------------------
// 3xBF16 tensor-core GEMM (unchanged R12): 2-stage ping-pong, one sync/chunk.
// ---------------------------------------------------------------------------
__global__ __launch_bounds__(256) void gemm_tc_kernel(
    const float* __restrict__ A, const float* __restrict__ Bm,
    const float* __restrict__ bias, float* __restrict__ out,
    const int* __restrict__ lidx, int N, int mode)
{
    const int K = 1024;
    extern __shared__ char smg[];
    uint32_t smB = (uint32_t)__cvta_generic_to_shared(smg);

    const float* Ap = (mode == 1) ? (const float*)g_attn : A;

    int tid = threadIdx.x;
    int bm = blockIdx.y;
    int bn = blockIdx.x;
    int lane = tid & 31, warp = tid >> 5;
    int wm = (warp >> 2) * 64;
    int wn = (warp & 3) * 32;
    int r = lane >> 2;
    int c = lane & 3;

    const float* Ab = Ap + (size_t)bm * 128 * K;
    const float* Bb = Bm + (size_t)bn * 128;

    int aM = tid >> 1;
    int aK = (tid & 1) * 16;
    int bK = tid >> 3;
    int bN = (tid & 7) * 4;

    int lr   = lane & 7;
    int lm8  = (lane >> 3) & 1;
    int lhi  = (lane >> 4) & 1;
    int aRowL = wm + lr + lm8 * 8;
    int bRowL = lr + lm8 * 8;

    uint32_t aStO = (uint32_t)aM * 80u + (uint32_t)aK * 2u;
    uint32_t bStO = (uint32_t)bK * 272u + (uint32_t)bN * 2u;

    float acc[4][4][4];
    #pragma unroll
    for (int mi = 0; mi < 4; mi++)
        #pragma unroll
        for (int ni = 0; ni < 4; ni++)
            #pragma unroll
            for (int e = 0; e < 4; e++) acc[mi][ni][e] = 0.f;

    float4 aPref[4];
    float4 bPref[4];
    #pragma unroll
    for (int j = 0; j < 4; j++) {
        aPref[j] = *(const float4*)(Ab + (size_t)aM * K + aK + j * 4);
        bPref[j] = *(const float4*)(Bb + (size_t)bK * N + bN + j * 32);
    }

    auto commit = [&](int s) {
        char* st = smg + s * G_STG;
        uint32_t hp[8], lp[8];
        #pragma unroll
        for (int j = 0; j < 4; j++) {
            bsplit2(aPref[j].x, aPref[j].y, hp[2*j],   lp[2*j]);
            bsplit2(aPref[j].z, aPref[j].w, hp[2*j+1], lp[2*j+1]);
        }
        *(uint4*)(st + aStO)              = make_uint4(hp[0], hp[1], hp[2], hp[3]);
        *(uint4*)(st + aStO + 16)         = make_uint4(hp[4], hp[5], hp[6], hp[7]);
        *(uint4*)(st + G_ALO + aStO)      = make_uint4(lp[0], lp[1], lp[2], lp[3]);
        *(uint4*)(st + G_ALO + aStO + 16) = make_uint4(lp[4], lp[5], lp[6], lp[7]);
        #pragma unroll
        for (int j = 0; j < 4; j++) {
            uint32_t h0, l0, h1, l1;
            bsplit2(bPref[j].x, bPref[j].y, h0, l0);
            bsplit2(bPref[j].z, bPref[j].w, h1, l1);
            *(uint2*)(st + G_BHI + bStO + j * 64) = make_uint2(h0, h1);
            *(uint2*)(st + G_BLO + bStO + j * 64) = make_uint2(l0, l1);
        }
    };

    commit(0);
    __syncthreads();

    const int NCHUNK = K / 32;
    for (int cI = 0; cI < NCHUNK; cI++) {
        if (cI + 1 < NCHUNK) {
            int k0 = (cI + 1) * 32;
            #pragma unroll
            for (int j = 0; j < 4; j++) {
                aPref[j] = *(const float4*)(Ab + (size_t)aM * K + k0 + aK + j * 4);
                bPref[j] = *(const float4*)(Bb + (size_t)(k0 + bK) * N + bN + j * 32);
            }
        }

        uint32_t stO = (uint32_t)(cI & 1) * G_STG;
        #pragma unroll
        for (int ks = 0; ks < 2; ks++) {
            uint32_t ahi[4][4], alo[4][4];
            #pragma unroll
            for (int mi = 0; mi < 4; mi++) {
                uint32_t off = stO + (uint32_t)(aRowL + mi * 16) * 80u + ks * 32u + lhi * 16u;
                ldsm_x4(ahi[mi][0], ahi[mi][1], ahi[mi][2], ahi[mi][3], smB + off);
                ldsm_x4(alo[mi][0], alo[mi][1], alo[mi][2], alo[mi][3], smB + G_ALO + off);
            }
            uint32_t bhi[2][4], blo[2][4];
            #pragma unroll
            for (int p = 0; p < 2; p++) {
                uint32_t off = stO + (uint32_t)(ks * 16 + bRowL) * 272u
                             + (uint32_t)(wn + p * 16 + lhi * 8) * 2u;
                ldsm_x4_t(bhi[p][0], bhi[p][1], bhi[p][2], bhi[p][3], smB + G_BHI + off);
                ldsm_x4_t(blo[p][0], blo[p][1], blo[p][2], blo[p][3], smB + G_BLO + off);
            }
            #pragma unroll
            for (int mi = 0; mi < 4; mi++)
                #pragma unroll
                for (int p = 0; p < 2; p++)
                    #pragma unroll
                    for (int q = 0; q < 2; q++) {
                        float* d = acc[mi][2 * p + q];
                        uint32_t b0h = bhi[p][2*q], b1h = bhi[p][2*q+1];
                        uint32_t b0l = blo[p][2*q], b1l = blo[p][2*q+1];
                        mma_bf16(d[0], d[1], d[2], d[3],
                                 ahi[mi][0], ahi[mi][1], ahi[mi][2], ahi[mi][3], b0h, b1h);
                        mma_bf16(d[0], d[1], d[2], d[3],
                                 ahi[mi][0], ahi[mi][1], ahi[mi][2], ahi[mi][3], b0l, b1l);
                        mma_bf16(d[0], d[1], d[2], d[3],
                                 alo[mi][0], alo[mi][1], alo[mi][2], alo[mi][3], b0h, b1h);
                    }
        }

        if (cI + 1 < NCHUNK)
            commit((cI + 1) & 1);
        __syncthreads();
    }

    if (mode == 0) {
        float scale = 0.125f / (float)(lidx[0] + 1);
        #pragma unroll
        for (int mi = 0; mi < 4; mi++) {
            #pragma unroll
            for (int ni = 0; ni < 4; ni++) {
                #pragma unroll
                for (int e = 0; e < 4; e++) {
                    int m = bm * 128 + wm + mi * 16 + r + (e >> 1) * 8;
                    int n = bn * 128 + wn + ni * 8 + c * 2 + (e & 1);
                    float v = acc[mi][ni][e] + bias[n];
                    int b = m >> 11, s = m & 2047;
                    int t = n >> 10;
                    int hd = n & 1023;
                    int h = hd >> 6, d = hd & 63;
                    size_t idx = ((size_t)(b * HSZ + h) * SSZ + s) * DSZ + d;
                    if (t == 0)      g_q[idx] = v * scale;
                    else if (t == 1) g_k[idx] = v;
                    else             g_v[idx] = v;
                }
            }
        }
    } else {
        #pragma unroll
        for (int mi = 0; mi < 4; mi++) {
            #pragma unroll
            for (int ni = 0; ni < 4; ni++) {
                #pragma unroll
                for (int e = 0; e < 4; e++) {
                    int m = bm * 128 + wm + mi * 16 + r + (e >> 1) * 8;
                    int n = bn * 128 + wn + ni * 8 + c * 2 + (e & 1);
                    out[(size_t)m * N + n] = acc[mi][ni][e] + bias[n];
                }
            }
        }
    }
}

// ---------------------------------------------------------------------------
// Tensor-core flash attention, R13: double-buffered K/V stages, ONE sync per
// tile, compute-first. QK tf32 via ldmatrix; PV 3xBF16 via ldmatrix.
// Smem: 2 stages x (K[64][68]tf32 + Vhi/Vlo[64][72]bf16) + Phi/Plo[128][72].
// ---------------------------------------------------------------------------
__global__ __launch_bounds__(256, 1) void attn_tc_kernel()
{
    extern __shared__ char smc[];
    uint32_t smB = (uint32_t)__cvta_generic_to_shared(smc);

    int bh = blockIdx.y;
    int qb = 15 - blockIdx.x;
    int q0 = qb * 128;

    const float* qp = g_q + (size_t)bh * SSZ * DSZ + (size_t)q0 * DSZ;
    const float* kb = g_k + (size_t)bh * SSZ * DSZ;
    const float* vb = g_v + (size_t)bh * SSZ * DSZ;

    int tid = threadIdx.x, lane = tid & 31, warp = tid >> 5;
    int r = lane >> 2, c = lane & 3;
    int wr0 = warp * 16;
    int lr  = lane & 7;
    int lm8 = (lane >> 3) & 1;
    int lhi = (lane >> 4) & 1;
    int g   = lane >> 3;
    int kdn = (g & 1) * 8;
    int kdk = (g >> 1) * 4;

    // Phase 1: Q -> smem (staging in stage-0 region) -> tf32 A-frags in regs
    {
        float (*Qs)[QPAD] = (float(*)[QPAD])smc;
        for (int i = tid; i < 128 * 16; i += 256) {
            int row = i >> 4, col4 = (i & 15) * 4;
            *(float4*)&Qs[row][col4] = *(const float4*)(qp + row * 64 + col4);
        }
        __syncthreads();
    }
    uint32_t qa[8][4];
    {
        float (*Qs)[QPAD] = (float(*)[QPAD])smc;
        #pragma unroll
        for (int ks = 0; ks < 8; ks++) {
            int k8 = ks * 8;
            qa[ks][0] = f2tf32(Qs[wr0 + r][k8 + c]);
            qa[ks][1] = f2tf32(Qs[wr0 + r + 8][k8 + c]);
            qa[ks][2] = f2tf32(Qs[wr0 + r][k8 + c + 4]);
            qa[ks][3] = f2tf32(Qs[wr0 + r + 8][k8 + c + 4]);
        }
        __syncthreads();   // all warps done reading Qs before stage-0 commit
    }

    float m0 = -1e30f, m1 = -1e30f, l0 = 0.f, l1 = 0.f;
    float o[8][4];
    #pragma unroll
    for (int ni = 0; ni < 8; ni++)
        #pragma unroll
        for (int e = 0; e < 4; e++) o[ni][e] = 0.f;

    int qrow0 = q0 + wr0 + r;
    int qrow1 = qrow0 + 8;

    // per-thread row/col for K/V tile loads (4 chunks of 256 threads)
    int rowT[4], colT[4];
    #pragma unroll
    for (int j = 0; j < 4; j++) {
        int i = tid + j * 256;
        rowT[j] = i >> 4;
        colT[j] = (i & 15) * 4;
    }

    float4 kPref[4], vPref[4];

    // commit prefetched K/V regs into stage s
    auto commitKV = [&](int s) {
        char* st = smc + s * A_STG;
        #pragma unroll
        for (int j = 0; j < 4; j++) {
            uint4 kt4;
            kt4.x = f2tf32(kPref[j].x); kt4.y = f2tf32(kPref[j].y);
            kt4.z = f2tf32(kPref[j].z); kt4.w = f2tf32(kPref[j].w);
            *(uint4*)(st + (uint32_t)rowT[j] * (KPADF*4) + (uint32_t)colT[j] * 4) = kt4;

            uint32_t h0, l0r, h1, l1r;
            bsplit2(vPref[j].x, vPref[j].y, h0, l0r);
            bsplit2(vPref[j].z, vPref[j].w, h1, l1r);
            *(uint2*)(st + A_VHI + (uint32_t)rowT[j] * (VPADB*2) + (uint32_t)colT[j] * 2) = make_uint2(h0, h1);
            *(uint2*)(st + A_VLO + (uint32_t)rowT[j] * (VPADB*2) + (uint32_t)colT[j] * 2) = make_uint2(l0r, l1r);
        }
    };

    // load tile 0 + commit to stage 0
    {
        const float* kp = kb;
        const float* vp = vb;
        #pragma unroll
        for (int j = 0; j < 4; j++) {
            kPref[j] = *(const float4*)(kp + rowT[j] * 64 + colT[j]);
            vPref[j] = *(const float4*)(vp + rowT[j] * 64 + colT[j]);
        }
        commitKV(0);
    }
    __syncthreads();

    int ntiles = (qb + 1) * 2;
    for (int kt = 0; kt < ntiles; kt++) {
        // prefetch next tile (LDG latency hidden under compute below)
        if (kt + 1 < ntiles) {
            const float* kp = kb + (size_t)(kt + 1) * 64 * DSZ;
            const float* vp = vb + (size_t)(kt + 1) * 64 * DSZ;
            #pragma unroll
            for (int j = 0; j < 4; j++) {
                kPref[j] = *(const float4*)(kp + rowT[j] * 64 + colT[j]);
                vPref[j] = *(const float4*)(vp + rowT[j] * 64 + colT[j]);
            }
        }

        uint32_t stO = (uint32_t)(kt & 1) * A_STG;

        // QK^T via ldmatrix tf32 B-frags
        float s[8][4];
        #pragma unroll
        for (int ni = 0; ni < 8; ni++)
            #pragma unroll
            for (int e = 0; e < 4; e++) s[ni][e] = 0.f;

        #pragma unroll
        for (int ks = 0; ks < 8; ks++) {
            int k8 = ks * 8;
            #pragma unroll
            for (int np = 0; np < 4; np++) {
                uint32_t kb0, kb1, kb2, kb3;
                uint32_t off = stO + (uint32_t)((np * 16 + kdn + lr) * KPADF + k8 + kdk) * 4u;
                ldsm_x4(kb0, kb1, kb2, kb3, smB + off);
                mma_tf32(s[2*np][0], s[2*np][1], s[2*np][2], s[2*np][3],
                         qa[ks][0], qa[ks][1], qa[ks][2], qa[ks][3], kb0, kb2);
                mma_tf32(s[2*np+1][0], s[2*np+1][1], s[2*np+1][2], s[2*np+1][3],
                         qa[ks][0], qa[ks][1], qa[ks][2], qa[ks][3], kb1, kb3);
            }
        }

        if (kt * 64 + 63 > qrow0) {
            #pragma unroll
            for (int ni = 0; ni < 8; ni++) {
                int key = kt * 64 + ni * 8 + 2 * c;
                if (key     > qrow0) s[ni][0] = -1e30f;
                if (key + 1 > qrow0) s[ni][1] = -1e30f;
                if (key     > qrow1) s[ni][2] = -1e30f;
                if (key + 1 > qrow1) s[ni][3] = -1e30f;
            }
        }

        float mx0 = -1e30f, mx1 = -1e30f;
        #pragma unroll
        for (int ni = 0; ni < 8; ni++) {
            mx0 = fmaxf(mx0, fmaxf(s[ni][0], s[ni][1]));
            mx1 = fmaxf(mx1, fmaxf(s[ni][2], s[ni][3]));
        }
        mx0 = fmaxf(mx0, __shfl_xor_sync(0xffffffffu, mx0, 1));
        mx0 = fmaxf(mx0, __shfl_xor_sync(0xffffffffu, mx0, 2));
        mx1 = fmaxf(mx1, __shfl_xor_sync(0xffffffffu, mx1, 1));
        mx1 = fmaxf(mx1, __shfl_xor_sync(0xffffffffu, mx1, 2));

        float mn0 = fmaxf(m0, mx0), mn1 = fmaxf(m1, mx1);
        float sum0 = 0.f, sum1 = 0.f;
        #pragma unroll
        for (int ni = 0; ni < 8; ni++) {
            float p0 = __expf(s[ni][0] - mn0);
            float p1 = __expf(s[ni][1] - mn0);
            float p2 = __expf(s[ni][2] - mn1);
            float p3 = __expf(s[ni][3] - mn1);
            sum0 += p0 + p1;
            sum1 += p2 + p3;
            uint32_t h, lw;
            int byte0 = A_PHI + (wr0 + r) * (PPADB*2) + (ni * 8 + 2 * c) * 2;
            int byte1 = A_PHI + (wr0 + r + 8) * (PPADB*2) + (ni * 8 + 2 * c) * 2;
            bsplit2(p0, p1, h, lw);
            *(uint32_t*)(smc + byte0) = h;
            *(uint32_t*)(smc + byte0 + (A_PLO - A_PHI)) = lw;
            bsplit2(p2, p3, h, lw);
            *(uint32_t*)(smc + byte1) = h;
            *(uint32_t*)(smc + byte1 + (A_PLO - A_PHI)) = lw;
        }
        sum0 += __shfl_xor_sync(0xffffffffu, sum0, 1);
        sum0 += __shfl_xor_sync(0xffffffffu, sum0, 2);
        sum1 += __shfl_xor_sync(0xffffffffu, sum1, 1);
        sum1 += __shfl_xor_sync(0xffffffffu, sum1, 2);

        float alpha0 = __expf(m0 - mn0);
        float alpha1 = __expf(m1 - mn1);
        l0 = l0 * alpha0 + sum0;  m0 = mn0;
        l1 = l1 * alpha1 + sum1;  m1 = mn1;
        #pragma unroll
        for (int ni = 0; ni < 8; ni++) {
            o[ni][0] *= alpha0; o[ni][1] *= alpha0;
            o[ni][2] *= alpha1; o[ni][3] *= alpha1;
        }
        __syncwarp();   // P rows are warp-private

        // PV: O += P * V (3xBF16 via ldmatrix)
        #pragma unroll
        for (int ks = 0; ks < 4; ks++) {
            uint32_t phf[4], plf[4];
            uint32_t offP = A_PHI + (uint32_t)(wr0 + lr + lm8 * 8) * (PPADB*2)
                          + (uint32_t)(ks * 16 + lhi * 8) * 2u;
            ldsm_x4(phf[0], phf[1], phf[2], phf[3], smB + offP);
            ldsm_x4(plf[0], plf[1], plf[2], plf[3], smB + offP + (A_PLO - A_PHI));

            uint32_t vhf[4][4], vlf[4][4];
            #pragma unroll
            for (int p = 0; p < 4; p++) {
                uint32_t offV = stO + A_VHI + (uint32_t)(ks * 16 + lr + lm8 * 8) * (VPADB*2)
                              + (uint32_t)(p * 16 + lhi * 8) * 2u;
                ldsm_x4_t(vhf[p][0], vhf[p][1], vhf[p][2], vhf[p][3], smB + offV);
                ldsm_x4_t(vlf[p][0], vlf[p][1], vlf[p][2], vlf[p][3], smB + offV + (A_VLO - A_VHI));
            }
            #pragma unroll
            for (int p = 0; p < 4; p++)
                #pragma unroll
                for (int q = 0; q < 2; q++) {
                    float* d = o[2 * p + q];
                    uint32_t b0h = vhf[p][2*q], b1h = vhf[p][2*q+1];
                    uint32_t b0l = vlf[p][2*q], b1l = vlf[p][2*q+1];
                    mma_bf16(d[0], d[1], d[2], d[3],
                             phf[0], phf[1], phf[2], phf[3], b0h, b1h);
                    mma_bf16(d[0], d[1], d[2], d[3],
                             phf[0], phf[1], phf[2], phf[3], b0l, b1l);
                    mma_bf16(d[0], d[1], d[2], d[3],
                             plf[0], plf[1], plf[2], plf[3], b0h, b1h);
                }
        }

        // commit next tile into the other stage (overlaps other warps' compute)
        if (kt + 1 < ntiles)
            commitKV((kt + 1) & 1);
        __syncthreads();
    }

    // Epilogue: normalize and write [B][S][H][D]
    int b = bh >> 4, h = bh & 15;
    float inv0 = 1.f / l0, inv1 = 1.f / l1;
    int s0 = q0 + wr0 + r, s1 = s0 + 8;
    size_t base0 = ((size_t)(b * SSZ + s0) * HSZ + h) * DSZ;
    size_t base1 = ((size_t)(b * SSZ + s1) * HSZ + h) * DSZ;
    #pragma unroll
    for (int ni = 0; ni < 8; ni++) {
        int d0 = ni * 8 + 2 * c;
        *(float2*)&g_attn[base0 + d0] = make_float2(o[ni][0] * inv0, o[ni][1] * inv0);
        *(float2*)&g_attn[base1 + d0] = make_float2(o[ni][2] * inv1, o[ni][3] * inv1);
    }
}

extern "C" void kernel_launch(void* const* d_in, const int* in_sizes, int n_in,
                              void* d_out, int out_size)
{
    const float* hidden = (const float*)d_in[0];
    const float* Wqkv  = (const float*)d_in[2];
    const float* bqkv  = (const float*)d_in[3];
    const float* Wproj = (const float*)d_in[4];
    const float* bproj = (const float*)d_in[5];
    const int*   lidx  = (const int*)d_in[6];
    float* out = (float*)d_out;

    cudaFuncSetAttribute(gemm_tc_kernel,
        cudaFuncAttributeMaxDynamicSharedMemorySize, G_TOTAL);
    cudaFuncSetAttribute(attn_tc_kernel,
        cudaFuncAttributeMaxDynamicSharedMemorySize, A_TOTAL);

    // QKV projection: M=8192, N=3072, K=1024
    gemm_tc_kernel<<<dim3(24, 64), 256, G_TOTAL>>>(hidden, Wqkv, bqkv, nullptr, lidx, 3072, 0);
    // Attention: 16 query tiles (128 rows each) x 64 (b,h) pairs
    attn_tc_kernel<<<dim3(16, 64), 256, A_TOTAL>>>();
    // Output projection: M=8192, N=1024, K=1024
    gemm_tc_kernel<<<dim3(8, 64), 256, G_TOTAL>>>(nullptr, Wproj, bproj, out, lidx, 1024, 1);
}